// round 1
// baseline (speedup 1.0000x reference)
#include <cuda_runtime.h>
#include <math.h>

#define DMODEL 1024
#define NHEADS 16
#define HD 64
#define BATCH 4
#define SEQ 2048
#define ROWS (BATCH * SEQ)   /* 8192 */
#define NQKV (3 * DMODEL)    /* 3072 */

// scale 1/sqrt(64)=0.125 folded with log2(e): softmax done in base 2
#define SC (0.125f * 1.44269504088896340736f)

// Scratch (allocation-free: __device__ globals)
__device__ float g_qkv[(size_t)ROWS * NQKV];   // 96 MB
__device__ float g_ctx[(size_t)ROWS * DMODEL]; // 32 MB

// ---------------------------------------------------------------------------
// C[M,N] = A[M,K] * B[N,K]^T + bias[N]    (both operands K-major, "NT" GEMM)
// 128x128 tile, BK=32, 256 threads, 8x8 per-thread microtile.
// ---------------------------------------------------------------------------
__global__ void __launch_bounds__(256, 2) gemm_nt_kernel(
    const float* __restrict__ A, const float* __restrict__ Bm,
    const float* __restrict__ bias, float* __restrict__ C,
    int M, int N, int K)
{
    __shared__ float As[32][132];   // [k][m], padded pitch
    __shared__ float Bs[32][132];   // [k][n]

    const int t  = threadIdx.x;
    const int tx = t & 15;          // n dir (16)
    const int ty = t >> 4;          // m dir (16)
    const int m0 = blockIdx.y * 128;
    const int n0 = blockIdx.x * 128;

    const float* Ab = A  + (size_t)m0 * K;
    const float* Bb = Bm + (size_t)n0 * K;

    float acc[8][8];
#pragma unroll
    for (int i = 0; i < 8; i++)
#pragma unroll
        for (int j = 0; j < 8; j++) acc[i][j] = 0.f;

    const int lrow = t >> 3;          // 0..31
    const int lc4  = (t & 7) * 4;     // 0..28

    for (int k0 = 0; k0 < K; k0 += 32) {
#pragma unroll
        for (int i = 0; i < 4; i++) {
            int row = lrow + i * 32;
            float4 va = *(const float4*)(Ab + (size_t)row * K + k0 + lc4);
            As[lc4 + 0][row] = va.x; As[lc4 + 1][row] = va.y;
            As[lc4 + 2][row] = va.z; As[lc4 + 3][row] = va.w;
            float4 vb = *(const float4*)(Bb + (size_t)row * K + k0 + lc4);
            Bs[lc4 + 0][row] = vb.x; Bs[lc4 + 1][row] = vb.y;
            Bs[lc4 + 2][row] = vb.z; Bs[lc4 + 3][row] = vb.w;
        }
        __syncthreads();
#pragma unroll
        for (int k = 0; k < 32; k++) {
            float a[8], b[8];
            *(float4*)(a)     = *(const float4*)&As[k][ty * 8];
            *(float4*)(a + 4) = *(const float4*)&As[k][ty * 8 + 4];
            *(float4*)(b)     = *(const float4*)&Bs[k][tx * 8];
            *(float4*)(b + 4) = *(const float4*)&Bs[k][tx * 8 + 4];
#pragma unroll
            for (int i = 0; i < 8; i++)
#pragma unroll
                for (int j = 0; j < 8; j++)
                    acc[i][j] = fmaf(a[i], b[j], acc[i][j]);
        }
        __syncthreads();
    }

    float bi[8];
#pragma unroll
    for (int j = 0; j < 8; j++) bi[j] = bias[n0 + tx * 8 + j];
#pragma unroll
    for (int i = 0; i < 8; i++) {
        int m = m0 + ty * 8 + i;
        float* Cr = C + (size_t)m * N + n0 + tx * 8;
        float4 o0 = { acc[i][0] + bi[0], acc[i][1] + bi[1],
                      acc[i][2] + bi[2], acc[i][3] + bi[3] };
        float4 o1 = { acc[i][4] + bi[4], acc[i][5] + bi[5],
                      acc[i][6] + bi[6], acc[i][7] + bi[7] };
        *(float4*)(Cr)     = o0;
        *(float4*)(Cr + 4) = o1;
    }
}

// ---------------------------------------------------------------------------
// Flash attention (fp32, online softmax, base-2 exponent).
// Grid: (SEQ/64, NHEADS, BATCH). 128 threads. Q tile 64, K/V tiles 64, hd=64.
// Per-thread microtile: 4 rows x 8 cols.
// ---------------------------------------------------------------------------
__global__ void __launch_bounds__(128) attn_kernel()
{
    extern __shared__ float sm[];
    float* Qs    = sm;                  // [64 d][68 m] transposed
    float* Ks    = Qs + 64 * 68;        // [64 d][68 n] transposed
    float* Vs    = Ks + 64 * 68;        // [64 n][64 d]
    float* Smem  = Vs + 64 * 64;        // [64 m][65 n] scores/probs
    float* row_m = Smem + 64 * 65;      // 64
    float* row_l = row_m + 64;          // 64
    float* row_c = row_l + 64;          // 64 correction factors
    float* pmax  = row_c + 64;          // [64][2]
    float* psum  = pmax + 128;          // [64][2]

    const int t  = threadIdx.x;
    const int tx = t & 7;               // col group (8)
    const int ty = t >> 3;              // row group (16)
    const int qt = blockIdx.x, h = blockIdx.y, b = blockIdx.z;
    const int q0 = qt * 64;

    const float* Qb = g_qkv + (size_t)(b * SEQ) * NQKV + h * HD;
    const float* Kb = Qb + DMODEL;
    const float* Vb = Qb + 2 * DMODEL;

    const int lrow = t >> 4;            // 0..7
    const int lc4  = (t & 15) * 4;      // 0..60

    // Load Q tile (transposed into [d][m])
#pragma unroll
    for (int i = 0; i < 8; i++) {
        int row = lrow + i * 8;
        float4 v = *(const float4*)(Qb + (size_t)(q0 + row) * NQKV + lc4);
        Qs[(lc4 + 0) * 68 + row] = v.x; Qs[(lc4 + 1) * 68 + row] = v.y;
        Qs[(lc4 + 2) * 68 + row] = v.z; Qs[(lc4 + 3) * 68 + row] = v.w;
    }
    if (t < 64) { row_m[t] = -1e30f; row_l[t] = 0.f; }

    float o[4][8];
#pragma unroll
    for (int i = 0; i < 4; i++)
#pragma unroll
        for (int j = 0; j < 8; j++) o[i][j] = 0.f;

    for (int n0 = 0; n0 < SEQ; n0 += 64) {
        __syncthreads();  // protect Ks/Vs/Smem reuse (and Q/stat init on iter 0)

        // Load K tile (transposed) and V tile (direct)
#pragma unroll
        for (int i = 0; i < 8; i++) {
            int row = lrow + i * 8;
            float4 v = *(const float4*)(Kb + (size_t)(n0 + row) * NQKV + lc4);
            Ks[(lc4 + 0) * 68 + row] = v.x; Ks[(lc4 + 1) * 68 + row] = v.y;
            Ks[(lc4 + 2) * 68 + row] = v.z; Ks[(lc4 + 3) * 68 + row] = v.w;
            float4 w = *(const float4*)(Vb + (size_t)(n0 + row) * NQKV + lc4);
            *(float4*)&Vs[row * 64 + lc4] = w;
        }
        __syncthreads();

        // S = Q K^T (scaled into base-2 domain)
        float s[4][8];
#pragma unroll
        for (int i = 0; i < 4; i++)
#pragma unroll
            for (int j = 0; j < 8; j++) s[i][j] = 0.f;

#pragma unroll 4
        for (int d = 0; d < 64; d++) {
            float a[4], bb[8];
            *(float4*)a        = *(const float4*)&Qs[d * 68 + ty * 4];
            *(float4*)(bb)     = *(const float4*)&Ks[d * 68 + tx * 8];
            *(float4*)(bb + 4) = *(const float4*)&Ks[d * 68 + tx * 8 + 4];
#pragma unroll
            for (int i = 0; i < 4; i++)
#pragma unroll
                for (int j = 0; j < 8; j++)
                    s[i][j] = fmaf(a[i], bb[j], s[i][j]);
        }
#pragma unroll
        for (int i = 0; i < 4; i++)
#pragma unroll
            for (int j = 0; j < 8; j++)
                Smem[(ty * 4 + i) * 65 + tx * 8 + j] = s[i][j] * SC;
        __syncthreads();

        // Online softmax row pass: 2 threads per row (balanced over all warps)
        {
            const int r  = t >> 1;
            const int hf = t & 1;
            float* Sr = Smem + r * 65 + hf * 32;
            float mx = Sr[0];
#pragma unroll
            for (int c = 1; c < 32; c++) mx = fmaxf(mx, Sr[c]);
            pmax[r * 2 + hf] = mx;
            __syncthreads();

            float m_new = fmaxf(row_m[r], fmaxf(pmax[r * 2], pmax[r * 2 + 1]));
            float sum = 0.f;
#pragma unroll
            for (int c = 0; c < 32; c++) {
                float p = exp2f(Sr[c] - m_new);
                Sr[c] = p;
                sum += p;
            }
            psum[r * 2 + hf] = sum;
            if (hf == 0) row_c[r] = exp2f(row_m[r] - m_new);
            __syncthreads();
            if (hf == 0) {
                row_l[r] = row_l[r] * row_c[r] + psum[r * 2] + psum[r * 2 + 1];
                row_m[r] = m_new;
            }
        }

        // O = O*corr + P V
        float cr[4];
#pragma unroll
        for (int i = 0; i < 4; i++) cr[i] = row_c[ty * 4 + i];
#pragma unroll
        for (int i = 0; i < 4; i++)
#pragma unroll
            for (int j = 0; j < 8; j++) o[i][j] *= cr[i];

#pragma unroll 2
        for (int n = 0; n < 64; n++) {
            float a[4], bb[8];
#pragma unroll
            for (int i = 0; i < 4; i++) a[i] = Smem[(ty * 4 + i) * 65 + n];
            *(float4*)(bb)     = *(const float4*)&Vs[n * 64 + tx * 8];
            *(float4*)(bb + 4) = *(const float4*)&Vs[n * 64 + tx * 8 + 4];
#pragma unroll
            for (int i = 0; i < 4; i++)
#pragma unroll
                for (int j = 0; j < 8; j++)
                    o[i][j] = fmaf(a[i], bb[j], o[i][j]);
        }
    }
    __syncthreads();

    float li[4];
#pragma unroll
    for (int i = 0; i < 4; i++) li[i] = 1.0f / row_l[ty * 4 + i];
#pragma unroll
    for (int i = 0; i < 4; i++) {
        int m = b * SEQ + q0 + ty * 4 + i;
        float* Cr = g_ctx + (size_t)m * DMODEL + h * HD + tx * 8;
        float4 o0 = { o[i][0] * li[i], o[i][1] * li[i],
                      o[i][2] * li[i], o[i][3] * li[i] };
        float4 o1 = { o[i][4] * li[i], o[i][5] * li[i],
                      o[i][6] * li[i], o[i][7] * li[i] };
        *(float4*)(Cr)     = o0;
        *(float4*)(Cr + 4) = o1;
    }
}

#define ATTN_SMEM_BYTES (17408 * 4)  /* 69632 B */

extern "C" void kernel_launch(void* const* d_in, const int* in_sizes, int n_in,
                              void* d_out, int out_size)
{
    const float* x     = (const float*)d_in[0];
    const float* qkv_w = (const float*)d_in[1];
    const float* qkv_b = (const float*)d_in[2];
    const float* out_w = (const float*)d_in[3];
    const float* out_b = (const float*)d_in[4];
    float* out = (float*)d_out;

    void* p_qkv = nullptr; void* p_ctx = nullptr;
    cudaGetSymbolAddress(&p_qkv, g_qkv);
    cudaGetSymbolAddress(&p_ctx, g_ctx);
    float* qkv = (float*)p_qkv;
    float* ctx = (float*)p_ctx;

    cudaFuncSetAttribute(attn_kernel,
                         cudaFuncAttributeMaxDynamicSharedMemorySize,
                         ATTN_SMEM_BYTES);

    // 1) QKV projection: [8192,3072] = x[8192,1024] @ qkv_w[3072,1024]^T + b
    gemm_nt_kernel<<<dim3(NQKV / 128, ROWS / 128), 256>>>(
        x, qkv_w, qkv_b, qkv, ROWS, NQKV, DMODEL);

    // 2) Fused flash attention -> ctx [8192,1024]
    attn_kernel<<<dim3(SEQ / 64, NHEADS, BATCH), 128, ATTN_SMEM_BYTES>>>();

    // 3) Output projection: out = ctx @ out_w^T + out_b
    gemm_nt_kernel<<<dim3(DMODEL / 128, ROWS / 128), 256>>>(
        ctx, out_w, out_b, out, ROWS, DMODEL, DMODEL);
}

// round 3
// speedup vs baseline: 1.1769x; 1.1769x over previous
#include <cuda_runtime.h>
#include <cuda_bf16.h>
#include <cstdint>
#include <math.h>

#define DMODEL 1024
#define NHEADS 16
#define HD 64
#define BATCH 4
#define SEQ 2048
#define ROWS (BATCH * SEQ)   /* 8192 */
#define NQKV (3 * DMODEL)    /* 3072 */

// softmax scale folded with log2(e) (base-2 softmax)
#define SC (0.125f * 1.44269504088896340736f)

// ---------------------------------------------------------------------------
// Scratch (allocation-free __device__ globals)
// ---------------------------------------------------------------------------
__device__ __align__(256) float g_qkv[(size_t)ROWS * NQKV];            // fp32 QKV
__device__ __align__(256) __nv_bfloat16 g_xh[(size_t)ROWS * DMODEL];
__device__ __align__(256) __nv_bfloat16 g_xl[(size_t)ROWS * DMODEL];
__device__ __align__(256) __nv_bfloat16 g_qwh[(size_t)NQKV * DMODEL];
__device__ __align__(256) __nv_bfloat16 g_qwl[(size_t)NQKV * DMODEL];
__device__ __align__(256) __nv_bfloat16 g_owh[(size_t)DMODEL * DMODEL];
__device__ __align__(256) __nv_bfloat16 g_owl[(size_t)DMODEL * DMODEL];
__device__ __align__(256) __nv_bfloat16 g_ch[(size_t)ROWS * DMODEL];   // ctx hi
__device__ __align__(256) __nv_bfloat16 g_cl[(size_t)ROWS * DMODEL];   // ctx lo

// ---------------------------------------------------------------------------
// helpers
// ---------------------------------------------------------------------------
__device__ __forceinline__ uint32_t smem_u32(const void* p) {
    return (uint32_t)__cvta_generic_to_shared(p);
}

__device__ __forceinline__ void split2(float a, float b, uint32_t& h, uint32_t& l) {
    __nv_bfloat16 ha = __float2bfloat16(a), hb = __float2bfloat16(b);
    __nv_bfloat16 la = __float2bfloat16(a - __bfloat162float(ha));
    __nv_bfloat16 lb = __float2bfloat16(b - __bfloat162float(hb));
    h = (uint32_t)__bfloat16_as_ushort(ha) | ((uint32_t)__bfloat16_as_ushort(hb) << 16);
    l = (uint32_t)__bfloat16_as_ushort(la) | ((uint32_t)__bfloat16_as_ushort(lb) << 16);
}

#define LDSM4(r, addr) \
    asm volatile("ldmatrix.sync.aligned.m8n8.x4.shared.b16 {%0,%1,%2,%3}, [%4];" \
                 : "=r"((r)[0]), "=r"((r)[1]), "=r"((r)[2]), "=r"((r)[3]) : "r"(addr))

#define MMA16816(d, a, b0, b1) \
    asm volatile("mma.sync.aligned.m16n8k16.row.col.f32.bf16.bf16.f32 " \
                 "{%0,%1,%2,%3}, {%4,%5,%6,%7}, {%8,%9}, {%0,%1,%2,%3};" \
                 : "+f"((d)[0]), "+f"((d)[1]), "+f"((d)[2]), "+f"((d)[3]) \
                 : "r"((a)[0]), "r"((a)[1]), "r"((a)[2]), "r"((a)[3]), \
                   "r"(b0), "r"(b1))

#define CP_ASYNC16(dst, src) \
    asm volatile("cp.async.cg.shared.global [%0], [%1], 16;" :: "r"(dst), "l"(src))
#define CP_COMMIT() asm volatile("cp.async.commit_group;" ::: "memory")
#define CP_WAIT1()  asm volatile("cp.async.wait_group 1;" ::: "memory")
#define CP_WAIT0()  asm volatile("cp.async.wait_group 0;" ::: "memory")

// ---------------------------------------------------------------------------
// Split fp32 -> bf16 hi/lo (vectorized 4-wide)
// ---------------------------------------------------------------------------
__global__ void split_kernel(const float4* __restrict__ in, uint2* __restrict__ hi,
                             uint2* __restrict__ lo, int n4) {
    int i = blockIdx.x * blockDim.x + threadIdx.x;
    if (i >= n4) return;
    float4 v = in[i];
    uint2 uh, ul;
    split2(v.x, v.y, uh.x, ul.x);
    split2(v.z, v.w, uh.y, ul.y);
    hi[i] = uh;
    lo[i] = ul;
}

// ---------------------------------------------------------------------------
// Tensor-core GEMM via mma.sync (bf16 hi/lo, 3-product fp32 emulation).
// C[M,N] = A[M,K]*B[N,K]^T + bias.  BM=BN=128, BK=32, 256 thr (8 warps),
// warp tile 64x32, 3-stage cp.async pipeline, 80B smem pitch.
// ---------------------------------------------------------------------------
#define BK 32
#define PITCHB 80                       /* bytes per smem row (40 bf16) */
#define ARR_BYTES (128 * PITCHB)        /* 10240 */
#define STG_BYTES (4 * ARR_BYTES)       /* 40960: Ah,Al,Bh,Bl */
#define GEMM_SMEM (3 * STG_BYTES)       /* 122880 */

__device__ __forceinline__ void load_stage(
    uint32_t sb, int k0, int t,
    const __nv_bfloat16* __restrict__ Ah, const __nv_bfloat16* __restrict__ Al,
    const __nv_bfloat16* __restrict__ Bh, const __nv_bfloat16* __restrict__ Bl,
    int m0, int n0, int K)
{
#pragma unroll
    for (int i = 0; i < 8; i++) {
        int idx = t + i * 256;
        int arr = idx >> 9;            // 0:Ah 1:Al 2:Bh 3:Bl
        int u   = idx & 511;
        int row = u & 127;
        int c   = u >> 7;              // 16B chunk 0..3
        const __nv_bfloat16* base = (arr == 0) ? Ah : (arr == 1) ? Al
                                   : (arr == 2) ? Bh : Bl;
        int grow = ((arr < 2) ? m0 : n0) + row;
        const __nv_bfloat16* src = base + (size_t)grow * K + k0 + c * 8;
        uint32_t dst = sb + arr * ARR_BYTES + row * PITCHB + c * 16;
        CP_ASYNC16(dst, src);
    }
}

__global__ void __launch_bounds__(256) gemm_tc(
    const __nv_bfloat16* __restrict__ Ah, const __nv_bfloat16* __restrict__ Al,
    const __nv_bfloat16* __restrict__ Bh, const __nv_bfloat16* __restrict__ Bl,
    const float* __restrict__ bias, float* __restrict__ C, int N, int K)
{
    extern __shared__ char dyn_smem[];
    const int t = threadIdx.x, wid = t >> 5, lane = t & 31;
    const int m0 = blockIdx.y * 128, n0 = blockIdx.x * 128;
    const int KT = K / BK;

    const uint32_t sbase = smem_u32(dyn_smem);
    const int wm = (wid >> 2) * 64;    // warp m origin
    const int wn = (wid & 3) * 32;     // warp n origin

    // ldmatrix lane addressing
    const int lmat = lane >> 3, lr = lane & 7;
    // A: mat order (m0-7,k0-7),(m8-15,k0-7),(m0-7,k8-15),(m8-15,k8-15)
    const uint32_t aOff = (uint32_t)((wm + (lmat & 1) * 8 + lr) * PITCHB + (lmat >> 1) * 16);
    // B: mat order (n0-7,k0-7),(n0-7,k8-15),(n8-15,k0-7),(n8-15,k8-15)
    const uint32_t bOff = (uint32_t)((wn + (lmat >> 1) * 8 + lr) * PITCHB + (lmat & 1) * 16);

    float acc[4][4][4];
#pragma unroll
    for (int i = 0; i < 4; i++)
#pragma unroll
        for (int j = 0; j < 4; j++)
#pragma unroll
            for (int r = 0; r < 4; r++) acc[i][j][r] = 0.f;

    load_stage(sbase + 0 * STG_BYTES, 0,  t, Ah, Al, Bh, Bl, m0, n0, K);
    CP_COMMIT();
    load_stage(sbase + 1 * STG_BYTES, BK, t, Ah, Al, Bh, Bl, m0, n0, K);
    CP_COMMIT();

    for (int kt = 0; kt < KT; kt++) {
        CP_WAIT1();
        __syncthreads();
        if (kt + 2 < KT)
            load_stage(sbase + ((kt + 2) % 3) * STG_BYTES, (kt + 2) * BK,
                       t, Ah, Al, Bh, Bl, m0, n0, K);
        CP_COMMIT();

        const uint32_t sb = sbase + (kt % 3) * STG_BYTES;
#pragma unroll
        for (int ks = 0; ks < 2; ks++) {
            uint32_t ah[4][4], al[4][4], bh[2][4], bl[2][4];
            const uint32_t kb = ks * 32;
#pragma unroll
            for (int mt = 0; mt < 4; mt++) {
                LDSM4(ah[mt], sb + 0 * ARR_BYTES + aOff + mt * (16 * PITCHB) + kb);
                LDSM4(al[mt], sb + 1 * ARR_BYTES + aOff + mt * (16 * PITCHB) + kb);
            }
#pragma unroll
            for (int j = 0; j < 2; j++) {
                LDSM4(bh[j], sb + 2 * ARR_BYTES + bOff + j * (16 * PITCHB) + kb);
                LDSM4(bl[j], sb + 3 * ARR_BYTES + bOff + j * (16 * PITCHB) + kb);
            }
            // pass 1: Ah*Bh ; pass 2: Ah*Bl ; pass 3: Al*Bh
#pragma unroll
            for (int mt = 0; mt < 4; mt++)
#pragma unroll
                for (int nt = 0; nt < 4; nt++)
                    MMA16816(acc[mt][nt], ah[mt],
                             bh[nt >> 1][(nt & 1) * 2], bh[nt >> 1][(nt & 1) * 2 + 1]);
#pragma unroll
            for (int mt = 0; mt < 4; mt++)
#pragma unroll
                for (int nt = 0; nt < 4; nt++)
                    MMA16816(acc[mt][nt], ah[mt],
                             bl[nt >> 1][(nt & 1) * 2], bl[nt >> 1][(nt & 1) * 2 + 1]);
#pragma unroll
            for (int mt = 0; mt < 4; mt++)
#pragma unroll
                for (int nt = 0; nt < 4; nt++)
                    MMA16816(acc[mt][nt], al[mt],
                             bh[nt >> 1][(nt & 1) * 2], bh[nt >> 1][(nt & 1) * 2 + 1]);
        }
    }
    CP_WAIT0();
    __syncthreads();

    // epilogue: stage C tile through smem for coalesced 128B stores
    float* Cs = (float*)dyn_smem;      // [128][132]
    const int g = lane >> 2, tg = lane & 3;
#pragma unroll
    for (int mt = 0; mt < 4; mt++)
#pragma unroll
        for (int nt = 0; nt < 4; nt++) {
            int r0 = wm + mt * 16 + g;
            int cc = wn + nt * 8 + tg * 2;
            Cs[r0 * 132 + cc]       = acc[mt][nt][0];
            Cs[r0 * 132 + cc + 1]   = acc[mt][nt][1];
            Cs[(r0 + 8) * 132 + cc]     = acc[mt][nt][2];
            Cs[(r0 + 8) * 132 + cc + 1] = acc[mt][nt][3];
        }
    __syncthreads();

    const int q = t & 31;              // float4 column group
    const int rb = t >> 5;             // row base 0..7
    float4 bv = *(const float4*)(bias + n0 + q * 4);
#pragma unroll
    for (int i = 0; i < 16; i++) {
        int row = rb + i * 8;
        float4 v = *(const float4*)&Cs[row * 132 + q * 4];
        v.x += bv.x; v.y += bv.y; v.z += bv.z; v.w += bv.w;
        *(float4*)(C + (size_t)(m0 + row) * N + n0 + q * 4) = v;
    }
}

// ---------------------------------------------------------------------------
// Flash attention (fp32, online softmax, base-2). Writes ctx as bf16 hi/lo.
// Grid: (SEQ/64, NHEADS, BATCH). 128 threads.
// ---------------------------------------------------------------------------
__global__ void __launch_bounds__(128) attn_kernel()
{
    extern __shared__ float sm[];
    float* Qs    = sm;                  // [64 d][68 m] transposed
    float* Ks    = Qs + 64 * 68;        // [64 d][68 n] transposed
    float* Vs    = Ks + 64 * 68;        // [64 n][64 d]
    float* Smem  = Vs + 64 * 64;        // [64 m][65 n]
    float* row_m = Smem + 64 * 65;
    float* row_l = row_m + 64;
    float* row_c = row_l + 64;
    float* pmax  = row_c + 64;          // [64][2]
    float* psum  = pmax + 128;          // [64][2]

    const int t  = threadIdx.x;
    const int tx = t & 7;
    const int ty = t >> 3;
    const int qt = blockIdx.x, h = blockIdx.y, b = blockIdx.z;
    const int q0 = qt * 64;

    const float* Qb = g_qkv + (size_t)(b * SEQ) * NQKV + h * HD;
    const float* Kb = Qb + DMODEL;
    const float* Vb = Qb + 2 * DMODEL;

    const int lrow = t >> 4;
    const int lc4  = (t & 15) * 4;

#pragma unroll
    for (int i = 0; i < 8; i++) {
        int row = lrow + i * 8;
        float4 v = *(const float4*)(Qb + (size_t)(q0 + row) * NQKV + lc4);
        Qs[(lc4 + 0) * 68 + row] = v.x; Qs[(lc4 + 1) * 68 + row] = v.y;
        Qs[(lc4 + 2) * 68 + row] = v.z; Qs[(lc4 + 3) * 68 + row] = v.w;
    }
    if (t < 64) { row_m[t] = -1e30f; row_l[t] = 0.f; }

    float o[4][8];
#pragma unroll
    for (int i = 0; i < 4; i++)
#pragma unroll
        for (int j = 0; j < 8; j++) o[i][j] = 0.f;

    for (int n0 = 0; n0 < SEQ; n0 += 64) {
        __syncthreads();
#pragma unroll
        for (int i = 0; i < 8; i++) {
            int row = lrow + i * 8;
            float4 v = *(const float4*)(Kb + (size_t)(n0 + row) * NQKV + lc4);
            Ks[(lc4 + 0) * 68 + row] = v.x; Ks[(lc4 + 1) * 68 + row] = v.y;
            Ks[(lc4 + 2) * 68 + row] = v.z; Ks[(lc4 + 3) * 68 + row] = v.w;
            float4 w = *(const float4*)(Vb + (size_t)(n0 + row) * NQKV + lc4);
            *(float4*)&Vs[row * 64 + lc4] = w;
        }
        __syncthreads();

        float s[4][8];
#pragma unroll
        for (int i = 0; i < 4; i++)
#pragma unroll
            for (int j = 0; j < 8; j++) s[i][j] = 0.f;

#pragma unroll 4
        for (int d = 0; d < 64; d++) {
            float a[4], bb[8];
            *(float4*)a        = *(const float4*)&Qs[d * 68 + ty * 4];
            *(float4*)(bb)     = *(const float4*)&Ks[d * 68 + tx * 8];
            *(float4*)(bb + 4) = *(const float4*)&Ks[d * 68 + tx * 8 + 4];
#pragma unroll
            for (int i = 0; i < 4; i++)
#pragma unroll
                for (int j = 0; j < 8; j++)
                    s[i][j] = fmaf(a[i], bb[j], s[i][j]);
        }
#pragma unroll
        for (int i = 0; i < 4; i++)
#pragma unroll
            for (int j = 0; j < 8; j++)
                Smem[(ty * 4 + i) * 65 + tx * 8 + j] = s[i][j] * SC;
        __syncthreads();

        {
            const int r  = t >> 1;
            const int hf = t & 1;
            float* Sr = Smem + r * 65 + hf * 32;
            float mx = Sr[0];
#pragma unroll
            for (int c = 1; c < 32; c++) mx = fmaxf(mx, Sr[c]);
            pmax[r * 2 + hf] = mx;
            __syncthreads();

            float m_new = fmaxf(row_m[r], fmaxf(pmax[r * 2], pmax[r * 2 + 1]));
            float sum = 0.f;
#pragma unroll
            for (int c = 0; c < 32; c++) {
                float p = exp2f(Sr[c] - m_new);
                Sr[c] = p;
                sum += p;
            }
            psum[r * 2 + hf] = sum;
            if (hf == 0) row_c[r] = exp2f(row_m[r] - m_new);
            __syncthreads();
            if (hf == 0) {
                row_l[r] = row_l[r] * row_c[r] + psum[r * 2] + psum[r * 2 + 1];
                row_m[r] = m_new;
            }
        }

        float cr[4];
#pragma unroll
        for (int i = 0; i < 4; i++) cr[i] = row_c[ty * 4 + i];
#pragma unroll
        for (int i = 0; i < 4; i++)
#pragma unroll
            for (int j = 0; j < 8; j++) o[i][j] *= cr[i];

#pragma unroll 2
        for (int n = 0; n < 64; n++) {
            float a[4], bb[8];
#pragma unroll
            for (int i = 0; i < 4; i++) a[i] = Smem[(ty * 4 + i) * 65 + n];
            *(float4*)(bb)     = *(const float4*)&Vs[n * 64 + tx * 8];
            *(float4*)(bb + 4) = *(const float4*)&Vs[n * 64 + tx * 8 + 4];
#pragma unroll
            for (int i = 0; i < 4; i++)
#pragma unroll
                for (int j = 0; j < 8; j++)
                    o[i][j] = fmaf(a[i], bb[j], o[i][j]);
        }
    }
    __syncthreads();

    float li[4];
#pragma unroll
    for (int i = 0; i < 4; i++) li[i] = 1.0f / row_l[ty * 4 + i];
#pragma unroll
    for (int i = 0; i < 4; i++) {
        int m = b * SEQ + q0 + ty * 4 + i;
        size_t base = (size_t)m * DMODEL + h * HD + tx * 8;
        uint4 H, L;
        split2(o[i][0] * li[i], o[i][1] * li[i], H.x, L.x);
        split2(o[i][2] * li[i], o[i][3] * li[i], H.y, L.y);
        split2(o[i][4] * li[i], o[i][5] * li[i], H.z, L.z);
        split2(o[i][6] * li[i], o[i][7] * li[i], H.w, L.w);
        *(uint4*)(g_ch + base) = H;
        *(uint4*)(g_cl + base) = L;
    }
}

#define ATTN_SMEM_BYTES (17408 * 4)  /* 69632 B */

extern "C" void kernel_launch(void* const* d_in, const int* in_sizes, int n_in,
                              void* d_out, int out_size)
{
    const float* x     = (const float*)d_in[0];
    const float* qkv_w = (const float*)d_in[1];
    const float* qkv_b = (const float*)d_in[2];
    const float* out_w = (const float*)d_in[3];
    const float* out_b = (const float*)d_in[4];
    float* out = (float*)d_out;

    void *p_qkv, *p_xh, *p_xl, *p_qwh, *p_qwl, *p_owh, *p_owl, *p_ch, *p_cl;
    cudaGetSymbolAddress(&p_qkv, g_qkv);
    cudaGetSymbolAddress(&p_xh, g_xh);   cudaGetSymbolAddress(&p_xl, g_xl);
    cudaGetSymbolAddress(&p_qwh, g_qwh); cudaGetSymbolAddress(&p_qwl, g_qwl);
    cudaGetSymbolAddress(&p_owh, g_owh); cudaGetSymbolAddress(&p_owl, g_owl);
    cudaGetSymbolAddress(&p_ch, g_ch);   cudaGetSymbolAddress(&p_cl, g_cl);

    cudaFuncSetAttribute(attn_kernel, cudaFuncAttributeMaxDynamicSharedMemorySize,
                         ATTN_SMEM_BYTES);
    cudaFuncSetAttribute(gemm_tc, cudaFuncAttributeMaxDynamicSharedMemorySize,
                         GEMM_SMEM);

    // split inputs to bf16 hi/lo
    {
        int n4 = ROWS * DMODEL / 4;
        split_kernel<<<(n4 + 255) / 256, 256>>>((const float4*)x, (uint2*)p_xh, (uint2*)p_xl, n4);
        n4 = NQKV * DMODEL / 4;
        split_kernel<<<(n4 + 255) / 256, 256>>>((const float4*)qkv_w, (uint2*)p_qwh, (uint2*)p_qwl, n4);
        n4 = DMODEL * DMODEL / 4;
        split_kernel<<<(n4 + 255) / 256, 256>>>((const float4*)out_w, (uint2*)p_owh, (uint2*)p_owl, n4);
    }

    // 1) QKV projection (mma.sync): [8192,3072]
    gemm_tc<<<dim3(NQKV / 128, ROWS / 128), 256, GEMM_SMEM>>>(
        (const __nv_bfloat16*)p_xh, (const __nv_bfloat16*)p_xl,
        (const __nv_bfloat16*)p_qwh, (const __nv_bfloat16*)p_qwl,
        qkv_b, (float*)p_qkv, NQKV, DMODEL);

    // 2) Flash attention -> ctx (bf16 hi/lo)
    attn_kernel<<<dim3(SEQ / 64, NHEADS, BATCH), 128, ATTN_SMEM_BYTES>>>();

    // 3) Output projection (mma.sync): [8192,1024]
    gemm_tc<<<dim3(DMODEL / 128, ROWS / 128), 256, GEMM_SMEM>>>(
        (const __nv_bfloat16*)p_ch, (const __nv_bfloat16*)p_cl,
        (const __nv_bfloat16*)p_owh, (const __nv_bfloat16*)p_owl,
        out_b, out, DMODEL, DMODEL);
}

// round 4
// speedup vs baseline: 2.6795x; 2.2766x over previous
#include <cuda_runtime.h>
#include <cuda_bf16.h>
#include <cstdint>
#include <math.h>

#define DMODEL 1024
#define NHEADS 16
#define HD 64
#define BATCH 4
#define SEQ 2048
#define ROWS (BATCH * SEQ)   /* 8192 */
#define NQKV (3 * DMODEL)    /* 3072 */

// softmax scale folded with log2(e) (base-2 softmax)
#define SC (0.125f * 1.44269504088896340736f)

// ---------------------------------------------------------------------------
// Scratch (allocation-free __device__ globals)
// ---------------------------------------------------------------------------
__device__ __align__(256) float g_qkv[(size_t)ROWS * NQKV];            // fp32 QKV
__device__ __align__(256) __nv_bfloat16 g_xh[(size_t)ROWS * DMODEL];
__device__ __align__(256) __nv_bfloat16 g_xl[(size_t)ROWS * DMODEL];
__device__ __align__(256) __nv_bfloat16 g_qwh[(size_t)NQKV * DMODEL];
__device__ __align__(256) __nv_bfloat16 g_qwl[(size_t)NQKV * DMODEL];
__device__ __align__(256) __nv_bfloat16 g_owh[(size_t)DMODEL * DMODEL];
__device__ __align__(256) __nv_bfloat16 g_owl[(size_t)DMODEL * DMODEL];
__device__ __align__(256) __nv_bfloat16 g_ch[(size_t)ROWS * DMODEL];   // ctx hi
__device__ __align__(256) __nv_bfloat16 g_cl[(size_t)ROWS * DMODEL];   // ctx lo
// per-head repacked attention operands (bf16 hi/lo)
__device__ __align__(256) __nv_bfloat16 g_Qh[(size_t)ROWS * DMODEL];
__device__ __align__(256) __nv_bfloat16 g_Ql[(size_t)ROWS * DMODEL];
__device__ __align__(256) __nv_bfloat16 g_Kh[(size_t)ROWS * DMODEL];
__device__ __align__(256) __nv_bfloat16 g_Kl[(size_t)ROWS * DMODEL];
__device__ __align__(256) __nv_bfloat16 g_Vth[(size_t)ROWS * DMODEL];  // [bh][d][s]
__device__ __align__(256) __nv_bfloat16 g_Vtl[(size_t)ROWS * DMODEL];

// ---------------------------------------------------------------------------
// helpers
// ---------------------------------------------------------------------------
__device__ __forceinline__ uint32_t smem_u32(const void* p) {
    return (uint32_t)__cvta_generic_to_shared(p);
}

__device__ __forceinline__ void split2(float a, float b, uint32_t& h, uint32_t& l) {
    __nv_bfloat16 ha = __float2bfloat16(a), hb = __float2bfloat16(b);
    __nv_bfloat16 la = __float2bfloat16(a - __bfloat162float(ha));
    __nv_bfloat16 lb = __float2bfloat16(b - __bfloat162float(hb));
    h = (uint32_t)__bfloat16_as_ushort(ha) | ((uint32_t)__bfloat16_as_ushort(hb) << 16);
    l = (uint32_t)__bfloat16_as_ushort(la) | ((uint32_t)__bfloat16_as_ushort(lb) << 16);
}

__device__ __forceinline__ float ex2(float x) {
    float y;
    asm("ex2.approx.ftz.f32 %0, %1;" : "=f"(y) : "f"(x));
    return y;
}

#define LDSM4(r, addr) \
    asm volatile("ldmatrix.sync.aligned.m8n8.x4.shared.b16 {%0,%1,%2,%3}, [%4];" \
                 : "=r"((r)[0]), "=r"((r)[1]), "=r"((r)[2]), "=r"((r)[3]) : "r"(addr))

#define MMA16816(d, a, b0, b1) \
    asm volatile("mma.sync.aligned.m16n8k16.row.col.f32.bf16.bf16.f32 " \
                 "{%0,%1,%2,%3}, {%4,%5,%6,%7}, {%8,%9}, {%0,%1,%2,%3};" \
                 : "+f"((d)[0]), "+f"((d)[1]), "+f"((d)[2]), "+f"((d)[3]) \
                 : "r"((a)[0]), "r"((a)[1]), "r"((a)[2]), "r"((a)[3]), \
                   "r"(b0), "r"(b1))

#define CP_ASYNC16(dst, src) \
    asm volatile("cp.async.cg.shared.global [%0], [%1], 16;" :: "r"(dst), "l"(src))
#define CP_COMMIT() asm volatile("cp.async.commit_group;" ::: "memory")
#define CP_WAIT1()  asm volatile("cp.async.wait_group 1;" ::: "memory")
#define CP_WAIT0()  asm volatile("cp.async.wait_group 0;" ::: "memory")

// ---------------------------------------------------------------------------
// Split fp32 -> bf16 hi/lo (vectorized 4-wide)
// ---------------------------------------------------------------------------
__global__ void split_kernel(const float4* __restrict__ in, uint2* __restrict__ hi,
                             uint2* __restrict__ lo, int n4) {
    int i = blockIdx.x * blockDim.x + threadIdx.x;
    if (i >= n4) return;
    float4 v = in[i];
    uint2 uh, ul;
    split2(v.x, v.y, uh.x, ul.x);
    split2(v.z, v.w, uh.y, ul.y);
    hi[i] = uh;
    lo[i] = ul;
}

// ---------------------------------------------------------------------------
// Repack Q,K from g_qkv fp32 -> per-head bf16 hi/lo: [bh][s][64]
// ---------------------------------------------------------------------------
__global__ void repack_qk_kernel() {
    int i = blockIdx.x * blockDim.x + threadIdx.x;     // one float4 of Q|K cols
    const int n4 = ROWS * 2048 / 4;
    if (i >= n4) return;
    int e   = i * 4;
    int row = e / 2048;
    int col = e % 2048;        // [0,1024)=Q, [1024,2048)=K
    float4 v = *(const float4*)(g_qkv + (size_t)row * NQKV + col);
    uint2 uh, ul;
    split2(v.x, v.y, uh.x, ul.x);
    split2(v.z, v.w, uh.y, ul.y);
    int hcol = col & 1023;
    int h = hcol >> 6, d = hcol & 63;
    int b = row >> 11, s = row & 2047;
    size_t dst = ((size_t)(b * NHEADS + h) * SEQ + s) * HD + d;
    if (col < 1024) {
        *(uint2*)(g_Qh + dst) = uh; *(uint2*)(g_Ql + dst) = ul;
    } else {
        *(uint2*)(g_Kh + dst) = uh; *(uint2*)(g_Kl + dst) = ul;
    }
}

// ---------------------------------------------------------------------------
// Repack V (transposed): g_qkv fp32 -> g_Vth/g_Vtl [bh][d][s]
// grid (SEQ/64, NHEADS, BATCH), 256 threads, smem transpose
// ---------------------------------------------------------------------------
__global__ void repack_v_kernel() {
    __shared__ float sm[64][65];
    const int t = threadIdx.x;
    const int st = blockIdx.x, hh = blockIdx.y, b = blockIdx.z;
#pragma unroll
    for (int i = 0; i < 16; i++) {
        int idx = t + i * 256;
        int r = idx >> 6, d = idx & 63;
        sm[d][r] = g_qkv[(size_t)(b * SEQ + st * 64 + r) * NQKV + 2048 + hh * HD + d];
    }
    __syncthreads();
#pragma unroll
    for (int i = 0; i < 8; i++) {
        int idx = t + i * 256;
        int dr = idx >> 5, sp = idx & 31;
        uint32_t uh, ul;
        split2(sm[dr][2 * sp], sm[dr][2 * sp + 1], uh, ul);
        size_t dst = ((size_t)(b * NHEADS + hh) * HD + dr) * SEQ + st * 64 + 2 * sp;
        *(uint32_t*)(g_Vth + dst) = uh;
        *(uint32_t*)(g_Vtl + dst) = ul;
    }
}

// ---------------------------------------------------------------------------
// Tensor-core GEMM via mma.sync (bf16 hi/lo, 3-product fp32 emulation).
// ---------------------------------------------------------------------------
#define BK 32
#define PITCHB 80
#define ARR_BYTES (128 * PITCHB)
#define STG_BYTES (4 * ARR_BYTES)
#define GEMM_SMEM (3 * STG_BYTES)

__device__ __forceinline__ void load_stage(
    uint32_t sb, int k0, int t,
    const __nv_bfloat16* __restrict__ Ah, const __nv_bfloat16* __restrict__ Al,
    const __nv_bfloat16* __restrict__ Bh, const __nv_bfloat16* __restrict__ Bl,
    int m0, int n0, int K)
{
#pragma unroll
    for (int i = 0; i < 8; i++) {
        int idx = t + i * 256;
        int arr = idx >> 9;
        int u   = idx & 511;
        int row = u & 127;
        int c   = u >> 7;
        const __nv_bfloat16* base = (arr == 0) ? Ah : (arr == 1) ? Al
                                   : (arr == 2) ? Bh : Bl;
        int grow = ((arr < 2) ? m0 : n0) + row;
        const __nv_bfloat16* src = base + (size_t)grow * K + k0 + c * 8;
        uint32_t dst = sb + arr * ARR_BYTES + row * PITCHB + c * 16;
        CP_ASYNC16(dst, src);
    }
}

__global__ void __launch_bounds__(256) gemm_tc(
    const __nv_bfloat16* __restrict__ Ah, const __nv_bfloat16* __restrict__ Al,
    const __nv_bfloat16* __restrict__ Bh, const __nv_bfloat16* __restrict__ Bl,
    const float* __restrict__ bias, float* __restrict__ C, int N, int K)
{
    extern __shared__ char dyn_smem[];
    const int t = threadIdx.x, wid = t >> 5, lane = t & 31;
    const int m0 = blockIdx.y * 128, n0 = blockIdx.x * 128;
    const int KT = K / BK;

    const uint32_t sbase = smem_u32(dyn_smem);
    const int wm = (wid >> 2) * 64;
    const int wn = (wid & 3) * 32;

    const int lmat = lane >> 3, lr = lane & 7;
    const uint32_t aOff = (uint32_t)((wm + (lmat & 1) * 8 + lr) * PITCHB + (lmat >> 1) * 16);
    const uint32_t bOff = (uint32_t)((wn + (lmat >> 1) * 8 + lr) * PITCHB + (lmat & 1) * 16);

    float acc[4][4][4];
#pragma unroll
    for (int i = 0; i < 4; i++)
#pragma unroll
        for (int j = 0; j < 4; j++)
#pragma unroll
            for (int r = 0; r < 4; r++) acc[i][j][r] = 0.f;

    load_stage(sbase + 0 * STG_BYTES, 0,  t, Ah, Al, Bh, Bl, m0, n0, K);
    CP_COMMIT();
    load_stage(sbase + 1 * STG_BYTES, BK, t, Ah, Al, Bh, Bl, m0, n0, K);
    CP_COMMIT();

    for (int kt = 0; kt < KT; kt++) {
        CP_WAIT1();
        __syncthreads();
        if (kt + 2 < KT)
            load_stage(sbase + ((kt + 2) % 3) * STG_BYTES, (kt + 2) * BK,
                       t, Ah, Al, Bh, Bl, m0, n0, K);
        CP_COMMIT();

        const uint32_t sb = sbase + (kt % 3) * STG_BYTES;
#pragma unroll
        for (int ks = 0; ks < 2; ks++) {
            uint32_t ah[4][4], al[4][4], bh[2][4], bl[2][4];
            const uint32_t kb = ks * 32;
#pragma unroll
            for (int mt = 0; mt < 4; mt++) {
                LDSM4(ah[mt], sb + 0 * ARR_BYTES + aOff + mt * (16 * PITCHB) + kb);
                LDSM4(al[mt], sb + 1 * ARR_BYTES + aOff + mt * (16 * PITCHB) + kb);
            }
#pragma unroll
            for (int j = 0; j < 2; j++) {
                LDSM4(bh[j], sb + 2 * ARR_BYTES + bOff + j * (16 * PITCHB) + kb);
                LDSM4(bl[j], sb + 3 * ARR_BYTES + bOff + j * (16 * PITCHB) + kb);
            }
#pragma unroll
            for (int mt = 0; mt < 4; mt++)
#pragma unroll
                for (int nt = 0; nt < 4; nt++)
                    MMA16816(acc[mt][nt], ah[mt],
                             bh[nt >> 1][(nt & 1) * 2], bh[nt >> 1][(nt & 1) * 2 + 1]);
#pragma unroll
            for (int mt = 0; mt < 4; mt++)
#pragma unroll
                for (int nt = 0; nt < 4; nt++)
                    MMA16816(acc[mt][nt], ah[mt],
                             bl[nt >> 1][(nt & 1) * 2], bl[nt >> 1][(nt & 1) * 2 + 1]);
#pragma unroll
            for (int mt = 0; mt < 4; mt++)
#pragma unroll
                for (int nt = 0; nt < 4; nt++)
                    MMA16816(acc[mt][nt], al[mt],
                             bh[nt >> 1][(nt & 1) * 2], bh[nt >> 1][(nt & 1) * 2 + 1]);
        }
    }
    CP_WAIT0();
    __syncthreads();

    float* Cs = (float*)dyn_smem;
    const int g = lane >> 2, tg = lane & 3;
#pragma unroll
    for (int mt = 0; mt < 4; mt++)
#pragma unroll
        for (int nt = 0; nt < 4; nt++) {
            int r0 = wm + mt * 16 + g;
            int cc = wn + nt * 8 + tg * 2;
            Cs[r0 * 132 + cc]       = acc[mt][nt][0];
            Cs[r0 * 132 + cc + 1]   = acc[mt][nt][1];
            Cs[(r0 + 8) * 132 + cc]     = acc[mt][nt][2];
            Cs[(r0 + 8) * 132 + cc + 1] = acc[mt][nt][3];
        }
    __syncthreads();

    const int q = t & 31;
    const int rb = t >> 5;
    float4 bv = *(const float4*)(bias + n0 + q * 4);
#pragma unroll
    for (int i = 0; i < 16; i++) {
        int row = rb + i * 8;
        float4 v = *(const float4*)&Cs[row * 132 + q * 4];
        v.x += bv.x; v.y += bv.y; v.z += bv.z; v.w += bv.w;
        *(float4*)(C + (size_t)(m0 + row) * N + n0 + q * 4) = v;
    }
}

// ---------------------------------------------------------------------------
// Tensor-core flash attention (bf16 hi/lo, 3-pass emulation both GEMMs).
// Grid (SEQ/64, NHEADS, BATCH), 128 threads (4 warps, 16 rows each).
// smem: Q hi/lo [64][64] + 2 stages of {Kh,Kl,Vth,Vtl} [64][64], pitch 144B.
// ---------------------------------------------------------------------------
#define APB 144                       /* attn smem pitch bytes */
#define AARR (64 * APB)               /* 9216 per array */
#define ASTG (4 * AARR)               /* 36864 per K/V stage */
#define ATTN_SMEM (2 * AARR + 2 * ASTG)   /* 92160 */

__global__ void __launch_bounds__(128) attn_tc(
    const __nv_bfloat16* __restrict__ Qh, const __nv_bfloat16* __restrict__ Ql,
    const __nv_bfloat16* __restrict__ Kh, const __nv_bfloat16* __restrict__ Kl,
    const __nv_bfloat16* __restrict__ Vth, const __nv_bfloat16* __restrict__ Vtl)
{
    extern __shared__ char dyn_smem[];
    const int t = threadIdx.x, wid = t >> 5, lane = t & 31;
    const int qt = blockIdx.x, h = blockIdx.y, b = blockIdx.z;
    const int bh = b * NHEADS + h;
    const int q0 = qt * 64;

    const uint32_t sQh = smem_u32(dyn_smem);
    const uint32_t sQl = sQh + AARR;
    const uint32_t sStg = sQl + AARR;     // stage s at sStg + s*ASTG

    const size_t qkBase = (size_t)bh * SEQ * HD;       // row-major [s][64]
    const size_t vBase  = (size_t)bh * HD * SEQ;       // row-major [d][2048]

    // ---- issue Q loads + stage 0 + stage 1 ----
    {
#pragma unroll
        for (int i = 0; i < 8; i++) {                  // Q hi/lo: 1024 chunks
            int idx = t + i * 128;
            int arr = idx >> 9;                        // 0:Qh 1:Ql
            int u = idx & 511, row = u >> 3, ch = u & 7;
            const __nv_bfloat16* src = (arr ? Ql : Qh) + qkBase + (size_t)(q0 + row) * HD + ch * 8;
            CP_ASYNC16(sQh + arr * AARR + row * APB + ch * 16, src);
        }
    }
#define LOAD_KV_STAGE(sbuf, kt0) do { \
    int kk0 = (kt0) * 64; \
    _Pragma("unroll") \
    for (int i = 0; i < 16; i++) { \
        int idx = t + i * 128; \
        int arr = idx >> 9; \
        int u = idx & 511, row = u >> 3, ch = u & 7; \
        const __nv_bfloat16* src; \
        if (arr == 0)      src = Kh  + qkBase + (size_t)(kk0 + row) * HD + ch * 8; \
        else if (arr == 1) src = Kl  + qkBase + (size_t)(kk0 + row) * HD + ch * 8; \
        else if (arr == 2) src = Vth + vBase + (size_t)row * SEQ + kk0 + ch * 8; \
        else               src = Vtl + vBase + (size_t)row * SEQ + kk0 + ch * 8; \
        CP_ASYNC16((sbuf) + arr * AARR + row * APB + ch * 16, src); \
    } \
} while (0)

    LOAD_KV_STAGE(sStg, 0);
    CP_COMMIT();                                       // group: Q + stage0
    LOAD_KV_STAGE(sStg + ASTG, 1);
    CP_COMMIT();

    // fragment addressing
    const int wm = wid * 16;
    const int lmat = lane >> 3, lr = lane & 7;
    const uint32_t aOff = (uint32_t)((wm + (lmat & 1) * 8 + lr) * APB + (lmat >> 1) * 16);
    const uint32_t bOff = (uint32_t)(((lmat >> 1) * 8 + lr) * APB + (lmat & 1) * 16);
    const int g = lane >> 2, tg = lane & 3;

    float O[8][4];
#pragma unroll
    for (int i = 0; i < 8; i++)
#pragma unroll
        for (int j = 0; j < 4; j++) O[i][j] = 0.f;
    float m0r = -1e30f, m1r = -1e30f, l0 = 0.f, l1 = 0.f;

    const int NKT = SEQ / 64;
    for (int kt = 0; kt < NKT; kt++) {
        CP_WAIT1();
        __syncthreads();
        const uint32_t sb = sStg + (kt & 1) * ASTG;
        const uint32_t sKh = sb, sKl = sb + AARR, sVh = sb + 2 * AARR, sVl = sb + 3 * AARR;

        // ---- S = Q K^T (3-pass hi/lo) ----
        float S[8][4];
#pragma unroll
        for (int i = 0; i < 8; i++)
#pragma unroll
            for (int j = 0; j < 4; j++) S[i][j] = 0.f;

#pragma unroll
        for (int kc = 0; kc < 4; kc++) {
            uint32_t qh[4], ql[4];
            LDSM4(qh, sQh + aOff + kc * 32);
            LDSM4(ql, sQl + aOff + kc * 32);
#pragma unroll
            for (int j = 0; j < 4; j++) {
                uint32_t kh[4], kl[4];
                LDSM4(kh, sKh + j * (16 * APB) + bOff + kc * 32);
                LDSM4(kl, sKl + j * (16 * APB) + bOff + kc * 32);
                MMA16816(S[2 * j],     qh, kh[0], kh[1]);
                MMA16816(S[2 * j + 1], qh, kh[2], kh[3]);
                MMA16816(S[2 * j],     qh, kl[0], kl[1]);
                MMA16816(S[2 * j + 1], qh, kl[2], kl[3]);
                MMA16816(S[2 * j],     ql, kh[0], kh[1]);
                MMA16816(S[2 * j + 1], ql, kh[2], kh[3]);
            }
        }

        // ---- online softmax (rows r0 = wm+g, r1 = r0+8) ----
        float rmax0 = -1e30f, rmax1 = -1e30f;
#pragma unroll
        for (int i = 0; i < 8; i++) {
            rmax0 = fmaxf(rmax0, fmaxf(S[i][0], S[i][1]));
            rmax1 = fmaxf(rmax1, fmaxf(S[i][2], S[i][3]));
        }
#pragma unroll
        for (int d = 1; d <= 2; d <<= 1) {
            rmax0 = fmaxf(rmax0, __shfl_xor_sync(0xffffffffu, rmax0, d));
            rmax1 = fmaxf(rmax1, __shfl_xor_sync(0xffffffffu, rmax1, d));
        }
        float mn0 = fmaxf(m0r, rmax0), mn1 = fmaxf(m1r, rmax1);
        float ms0 = mn0 * SC, ms1 = mn1 * SC;
        float sum0 = 0.f, sum1 = 0.f;
#pragma unroll
        for (int i = 0; i < 8; i++) {
            S[i][0] = ex2(fmaf(S[i][0], SC, -ms0));
            S[i][1] = ex2(fmaf(S[i][1], SC, -ms0));
            S[i][2] = ex2(fmaf(S[i][2], SC, -ms1));
            S[i][3] = ex2(fmaf(S[i][3], SC, -ms1));
            sum0 += S[i][0] + S[i][1];
            sum1 += S[i][2] + S[i][3];
        }
#pragma unroll
        for (int d = 1; d <= 2; d <<= 1) {
            sum0 += __shfl_xor_sync(0xffffffffu, sum0, d);
            sum1 += __shfl_xor_sync(0xffffffffu, sum1, d);
        }
        float c0 = ex2(SC * (m0r - mn0)), c1 = ex2(SC * (m1r - mn1));
        l0 = l0 * c0 + sum0;
        l1 = l1 * c1 + sum1;
        m0r = mn0; m1r = mn1;
#pragma unroll
        for (int i = 0; i < 8; i++) {
            O[i][0] *= c0; O[i][1] *= c0;
            O[i][2] *= c1; O[i][3] *= c1;
        }

        // ---- O += P V (3-pass hi/lo) ----
#pragma unroll
        for (int kg = 0; kg < 4; kg++) {
            uint32_t ph[4], pl[4];
            split2(S[2 * kg][0],     S[2 * kg][1],     ph[0], pl[0]);
            split2(S[2 * kg][2],     S[2 * kg][3],     ph[1], pl[1]);
            split2(S[2 * kg + 1][0], S[2 * kg + 1][1], ph[2], pl[2]);
            split2(S[2 * kg + 1][2], S[2 * kg + 1][3], ph[3], pl[3]);
#pragma unroll
            for (int dn = 0; dn < 4; dn++) {
                uint32_t vh[4], vl[4];
                LDSM4(vh, sVh + dn * (16 * APB) + bOff + kg * 32);
                LDSM4(vl, sVl + dn * (16 * APB) + bOff + kg * 32);
                MMA16816(O[2 * dn],     ph, vh[0], vh[1]);
                MMA16816(O[2 * dn + 1], ph, vh[2], vh[3]);
                MMA16816(O[2 * dn],     ph, vl[0], vl[1]);
                MMA16816(O[2 * dn + 1], ph, vl[2], vl[3]);
                MMA16816(O[2 * dn],     pl, vh[0], vh[1]);
                MMA16816(O[2 * dn + 1], pl, vh[2], vh[3]);
            }
        }

        __syncthreads();
        if (kt + 2 < NKT) {
            LOAD_KV_STAGE(sStg + (kt & 1) * ASTG, kt + 2);
        }
        CP_COMMIT();
    }

    // ---- normalize + store ctx (bf16 hi/lo) ----
    float inv0 = 1.0f / l0, inv1 = 1.0f / l1;
    int r0 = b * SEQ + q0 + wm + g;
    int r1 = r0 + 8;
#pragma unroll
    for (int ot = 0; ot < 8; ot++) {
        int col = h * HD + ot * 8 + tg * 2;
        uint32_t uh, ul;
        split2(O[ot][0] * inv0, O[ot][1] * inv0, uh, ul);
        *(uint32_t*)(g_ch + (size_t)r0 * DMODEL + col) = uh;
        *(uint32_t*)(g_cl + (size_t)r0 * DMODEL + col) = ul;
        split2(O[ot][2] * inv1, O[ot][3] * inv1, uh, ul);
        *(uint32_t*)(g_ch + (size_t)r1 * DMODEL + col) = uh;
        *(uint32_t*)(g_cl + (size_t)r1 * DMODEL + col) = ul;
    }
}

extern "C" void kernel_launch(void* const* d_in, const int* in_sizes, int n_in,
                              void* d_out, int out_size)
{
    const float* x     = (const float*)d_in[0];
    const float* qkv_w = (const float*)d_in[1];
    const float* qkv_b = (const float*)d_in[2];
    const float* out_w = (const float*)d_in[3];
    const float* out_b = (const float*)d_in[4];
    float* out = (float*)d_out;

    void *p_qkv, *p_xh, *p_xl, *p_qwh, *p_qwl, *p_owh, *p_owl, *p_ch, *p_cl;
    void *p_Qh, *p_Ql, *p_Kh, *p_Kl, *p_Vth, *p_Vtl;
    cudaGetSymbolAddress(&p_qkv, g_qkv);
    cudaGetSymbolAddress(&p_xh, g_xh);   cudaGetSymbolAddress(&p_xl, g_xl);
    cudaGetSymbolAddress(&p_qwh, g_qwh); cudaGetSymbolAddress(&p_qwl, g_qwl);
    cudaGetSymbolAddress(&p_owh, g_owh); cudaGetSymbolAddress(&p_owl, g_owl);
    cudaGetSymbolAddress(&p_ch, g_ch);   cudaGetSymbolAddress(&p_cl, g_cl);
    cudaGetSymbolAddress(&p_Qh, g_Qh);   cudaGetSymbolAddress(&p_Ql, g_Ql);
    cudaGetSymbolAddress(&p_Kh, g_Kh);   cudaGetSymbolAddress(&p_Kl, g_Kl);
    cudaGetSymbolAddress(&p_Vth, g_Vth); cudaGetSymbolAddress(&p_Vtl, g_Vtl);

    cudaFuncSetAttribute(gemm_tc, cudaFuncAttributeMaxDynamicSharedMemorySize,
                         GEMM_SMEM);
    cudaFuncSetAttribute(attn_tc, cudaFuncAttributeMaxDynamicSharedMemorySize,
                         ATTN_SMEM);

    // split weights/x to bf16 hi/lo
    {
        int n4 = ROWS * DMODEL / 4;
        split_kernel<<<(n4 + 255) / 256, 256>>>((const float4*)x, (uint2*)p_xh, (uint2*)p_xl, n4);
        n4 = NQKV * DMODEL / 4;
        split_kernel<<<(n4 + 255) / 256, 256>>>((const float4*)qkv_w, (uint2*)p_qwh, (uint2*)p_qwl, n4);
        n4 = DMODEL * DMODEL / 4;
        split_kernel<<<(n4 + 255) / 256, 256>>>((const float4*)out_w, (uint2*)p_owh, (uint2*)p_owl, n4);
    }

    // 1) QKV projection
    gemm_tc<<<dim3(NQKV / 128, ROWS / 128), 256, GEMM_SMEM>>>(
        (const __nv_bfloat16*)p_xh, (const __nv_bfloat16*)p_xl,
        (const __nv_bfloat16*)p_qwh, (const __nv_bfloat16*)p_qwl,
        qkv_b, (float*)p_qkv, NQKV, DMODEL);

    // 2) repack QKV for attention
    {
        int n4 = ROWS * 2048 / 4;
        repack_qk_kernel<<<(n4 + 255) / 256, 256>>>();
        repack_v_kernel<<<dim3(SEQ / 64, NHEADS, BATCH), 256>>>();
    }

    // 3) tensor-core flash attention -> ctx (bf16 hi/lo)
    attn_tc<<<dim3(SEQ / 64, NHEADS, BATCH), 128, ATTN_SMEM>>>(
        (const __nv_bfloat16*)p_Qh, (const __nv_bfloat16*)p_Ql,
        (const __nv_bfloat16*)p_Kh, (const __nv_bfloat16*)p_Kl,
        (const __nv_bfloat16*)p_Vth, (const __nv_bfloat16*)p_Vtl);

    // 4) output projection
    gemm_tc<<<dim3(DMODEL / 128, ROWS / 128), 256, GEMM_SMEM>>>(
        (const __nv_bfloat16*)p_ch, (const __nv_bfloat16*)p_cl,
        (const __nv_bfloat16*)p_owh, (const __nv_bfloat16*)p_owl,
        out_b, out, DMODEL, DMODEL);
}

// round 6
// speedup vs baseline: 3.0320x; 1.1316x over previous
#include <cuda_runtime.h>
#include <cuda_bf16.h>
#include <cstdint>
#include <math.h>

#define DMODEL 1024
#define NHEADS 16
#define HD 64
#define BATCH 4
#define SEQ 2048
#define ROWS (BATCH * SEQ)   /* 8192 */
#define NQKV (3 * DMODEL)    /* 3072 */

// softmax scale folded with log2(e) (base-2 softmax)
#define SC (0.125f * 1.44269504088896340736f)

// ---------------------------------------------------------------------------
// Scratch (allocation-free __device__ globals)
// ---------------------------------------------------------------------------
__device__ __align__(256) __nv_bfloat16 g_xh[(size_t)ROWS * DMODEL];
__device__ __align__(256) __nv_bfloat16 g_xl[(size_t)ROWS * DMODEL];
__device__ __align__(256) __nv_bfloat16 g_qwh[(size_t)NQKV * DMODEL];
__device__ __align__(256) __nv_bfloat16 g_qwl[(size_t)NQKV * DMODEL];
__device__ __align__(256) __nv_bfloat16 g_owh[(size_t)DMODEL * DMODEL];
__device__ __align__(256) __nv_bfloat16 g_owl[(size_t)DMODEL * DMODEL];
__device__ __align__(256) __nv_bfloat16 g_ch[(size_t)ROWS * DMODEL];   // ctx hi
__device__ __align__(256) __nv_bfloat16 g_cl[(size_t)ROWS * DMODEL];   // ctx lo
// per-head attention operands (bf16 hi/lo), written by fused QKV epilogue
__device__ __align__(256) __nv_bfloat16 g_Qh[(size_t)ROWS * DMODEL];
__device__ __align__(256) __nv_bfloat16 g_Ql[(size_t)ROWS * DMODEL];
__device__ __align__(256) __nv_bfloat16 g_Kh[(size_t)ROWS * DMODEL];
__device__ __align__(256) __nv_bfloat16 g_Kl[(size_t)ROWS * DMODEL];
__device__ __align__(256) __nv_bfloat16 g_Vth[(size_t)ROWS * DMODEL];  // [bh][d][s]
__device__ __align__(256) __nv_bfloat16 g_Vtl[(size_t)ROWS * DMODEL];

// ---------------------------------------------------------------------------
// helpers
// ---------------------------------------------------------------------------
__device__ __forceinline__ uint32_t smem_u32(const void* p) {
    return (uint32_t)__cvta_generic_to_shared(p);
}

__device__ __forceinline__ void split2(float a, float b, uint32_t& h, uint32_t& l) {
    __nv_bfloat16 ha = __float2bfloat16(a), hb = __float2bfloat16(b);
    __nv_bfloat16 la = __float2bfloat16(a - __bfloat162float(ha));
    __nv_bfloat16 lb = __float2bfloat16(b - __bfloat162float(hb));
    h = (uint32_t)__bfloat16_as_ushort(ha) | ((uint32_t)__bfloat16_as_ushort(hb) << 16);
    l = (uint32_t)__bfloat16_as_ushort(la) | ((uint32_t)__bfloat16_as_ushort(lb) << 16);
}

__device__ __forceinline__ float ex2(float x) {
    float y;
    asm("ex2.approx.ftz.f32 %0, %1;" : "=f"(y) : "f"(x));
    return y;
}

#define LDSM4(r, addr) \
    asm volatile("ldmatrix.sync.aligned.m8n8.x4.shared.b16 {%0,%1,%2,%3}, [%4];" \
                 : "=r"((r)[0]), "=r"((r)[1]), "=r"((r)[2]), "=r"((r)[3]) : "r"(addr))

#define MMA16816(d, a, b0, b1) \
    asm volatile("mma.sync.aligned.m16n8k16.row.col.f32.bf16.bf16.f32 " \
                 "{%0,%1,%2,%3}, {%4,%5,%6,%7}, {%8,%9}, {%0,%1,%2,%3};" \
                 : "+f"((d)[0]), "+f"((d)[1]), "+f"((d)[2]), "+f"((d)[3]) \
                 : "r"((a)[0]), "r"((a)[1]), "r"((a)[2]), "r"((a)[3]), \
                   "r"(b0), "r"(b1))

#define CP_ASYNC16(dst, src) \
    asm volatile("cp.async.cg.shared.global [%0], [%1], 16;" :: "r"(dst), "l"(src))
#define CP_COMMIT() asm volatile("cp.async.commit_group;" ::: "memory")
#define CP_WAIT1()  asm volatile("cp.async.wait_group 1;" ::: "memory")
#define CP_WAIT0()  asm volatile("cp.async.wait_group 0;" ::: "memory")

// ---------------------------------------------------------------------------
// Split fp32 -> bf16 hi/lo (vectorized 4-wide)
// ---------------------------------------------------------------------------
__global__ void split_kernel(const float4* __restrict__ in, uint2* __restrict__ hi,
                             uint2* __restrict__ lo, int n4) {
    int i = blockIdx.x * blockDim.x + threadIdx.x;
    if (i >= n4) return;
    float4 v = in[i];
    uint2 uh, ul;
    split2(v.x, v.y, uh.x, ul.x);
    split2(v.z, v.w, uh.y, ul.y);
    hi[i] = uh;
    lo[i] = ul;
}

// ---------------------------------------------------------------------------
// Tensor-core GEMM via mma.sync (bf16 hi/lo, 3-product fp32 emulation).
// C[M,N] = A[M,K]*B[N,K]^T + bias.  BM=BN=128, BK=32, 256 thr (8 warps),
// warp tile 64x32, 2-stage cp.async pipeline -> 2 CTAs/SM.
// QKV_EPI: instead of fp32 C, write Q/K per-head bf16 hi/lo and V transposed.
// ---------------------------------------------------------------------------
#define BK 32
#define PITCHB 80
#define ARR_BYTES (128 * PITCHB)        /* 10240 */
#define STG_BYTES (4 * ARR_BYTES)       /* 40960 */
#define GEMM_SMEM (2 * STG_BYTES)       /* 81920 */
#define CPITCH 132                      /* C staging pitch (floats) */

__device__ __forceinline__ void load_stage(
    uint32_t sb, int k0, int t,
    const __nv_bfloat16* __restrict__ Ah, const __nv_bfloat16* __restrict__ Al,
    const __nv_bfloat16* __restrict__ Bh, const __nv_bfloat16* __restrict__ Bl,
    int m0, int n0, int K)
{
#pragma unroll
    for (int i = 0; i < 8; i++) {
        int idx = t + i * 256;
        int arr = idx >> 9;
        int u   = idx & 511;
        int row = u & 127;
        int c   = u >> 7;
        const __nv_bfloat16* base = (arr == 0) ? Ah : (arr == 1) ? Al
                                   : (arr == 2) ? Bh : Bl;
        int grow = ((arr < 2) ? m0 : n0) + row;
        const __nv_bfloat16* src = base + (size_t)grow * K + k0 + c * 8;
        uint32_t dst = sb + arr * ARR_BYTES + row * PITCHB + c * 16;
        CP_ASYNC16(dst, src);
    }
}

template <bool QKV_EPI>
__global__ void __launch_bounds__(256, 2) gemm_tc(
    const __nv_bfloat16* __restrict__ Ah, const __nv_bfloat16* __restrict__ Al,
    const __nv_bfloat16* __restrict__ Bh, const __nv_bfloat16* __restrict__ Bl,
    const float* __restrict__ bias, float* __restrict__ C, int N, int K)
{
    extern __shared__ char dyn_smem[];
    const int t = threadIdx.x, wid = t >> 5, lane = t & 31;
    const int m0 = blockIdx.y * 128, n0 = blockIdx.x * 128;
    const int KT = K / BK;

    const uint32_t sbase = smem_u32(dyn_smem);
    const int wm = (wid >> 2) * 64;
    const int wn = (wid & 3) * 32;

    const int lmat = lane >> 3, lr = lane & 7;
    const uint32_t aOff = (uint32_t)((wm + (lmat & 1) * 8 + lr) * PITCHB + (lmat >> 1) * 16);
    const uint32_t bOff = (uint32_t)((wn + (lmat >> 1) * 8 + lr) * PITCHB + (lmat & 1) * 16);

    float acc[4][4][4];
#pragma unroll
    for (int i = 0; i < 4; i++)
#pragma unroll
        for (int j = 0; j < 4; j++)
#pragma unroll
            for (int r = 0; r < 4; r++) acc[i][j][r] = 0.f;

    load_stage(sbase + 0 * STG_BYTES, 0,  t, Ah, Al, Bh, Bl, m0, n0, K);
    CP_COMMIT();
    load_stage(sbase + 1 * STG_BYTES, BK, t, Ah, Al, Bh, Bl, m0, n0, K);
    CP_COMMIT();

    for (int kt = 0; kt < KT; kt++) {
        CP_WAIT1();
        __syncthreads();

        const uint32_t sb = sbase + (kt & 1) * STG_BYTES;
#pragma unroll
        for (int ks = 0; ks < 2; ks++) {
            uint32_t ah[4][4], al[4][4], bh[2][4], bl[2][4];
            const uint32_t kb = ks * 32;
#pragma unroll
            for (int mt = 0; mt < 4; mt++) {
                LDSM4(ah[mt], sb + 0 * ARR_BYTES + aOff + mt * (16 * PITCHB) + kb);
                LDSM4(al[mt], sb + 1 * ARR_BYTES + aOff + mt * (16 * PITCHB) + kb);
            }
#pragma unroll
            for (int j = 0; j < 2; j++) {
                LDSM4(bh[j], sb + 2 * ARR_BYTES + bOff + j * (16 * PITCHB) + kb);
                LDSM4(bl[j], sb + 3 * ARR_BYTES + bOff + j * (16 * PITCHB) + kb);
            }
#pragma unroll
            for (int mt = 0; mt < 4; mt++)
#pragma unroll
                for (int nt = 0; nt < 4; nt++)
                    MMA16816(acc[mt][nt], ah[mt],
                             bh[nt >> 1][(nt & 1) * 2], bh[nt >> 1][(nt & 1) * 2 + 1]);
#pragma unroll
            for (int mt = 0; mt < 4; mt++)
#pragma unroll
                for (int nt = 0; nt < 4; nt++)
                    MMA16816(acc[mt][nt], ah[mt],
                             bl[nt >> 1][(nt & 1) * 2], bl[nt >> 1][(nt & 1) * 2 + 1]);
#pragma unroll
            for (int mt = 0; mt < 4; mt++)
#pragma unroll
                for (int nt = 0; nt < 4; nt++)
                    MMA16816(acc[mt][nt], al[mt],
                             bh[nt >> 1][(nt & 1) * 2], bh[nt >> 1][(nt & 1) * 2 + 1]);
        }

        __syncthreads();
        if (kt + 2 < KT)
            load_stage(sbase + (kt & 1) * STG_BYTES, (kt + 2) * BK,
                       t, Ah, Al, Bh, Bl, m0, n0, K);
        CP_COMMIT();
    }
    CP_WAIT0();
    __syncthreads();

    const int g = lane >> 2, tg = lane & 3;

    if (!QKV_EPI) {
        // epilogue: stage C tile through smem for coalesced 128B fp32 stores
        float* Cs = (float*)dyn_smem;      // [128][CPITCH]
#pragma unroll
        for (int mt = 0; mt < 4; mt++)
#pragma unroll
            for (int nt = 0; nt < 4; nt++) {
                int r0 = wm + mt * 16 + g;
                int cc = wn + nt * 8 + tg * 2;
                Cs[r0 * CPITCH + cc]       = acc[mt][nt][0];
                Cs[r0 * CPITCH + cc + 1]   = acc[mt][nt][1];
                Cs[(r0 + 8) * CPITCH + cc]     = acc[mt][nt][2];
                Cs[(r0 + 8) * CPITCH + cc + 1] = acc[mt][nt][3];
            }
        __syncthreads();

        const int q = t & 31;
        const int rb = t >> 5;
        float4 bv = *(const float4*)(bias + n0 + q * 4);
#pragma unroll
        for (int i = 0; i < 16; i++) {
            int row = rb + i * 8;
            float4 v = *(const float4*)&Cs[row * CPITCH + q * 4];
            v.x += bv.x; v.y += bv.y; v.z += bv.z; v.w += bv.w;
            *(float4*)(C + (size_t)(m0 + row) * N + n0 + q * 4) = v;
        }
    } else {
        // fused QKV epilogue: bias + split + per-head scatter (V transposed)
        float* Cs = (float*)dyn_smem;      // [128][CPITCH]
        float bv[4][2];
#pragma unroll
        for (int nt = 0; nt < 4; nt++) {
            int gc = n0 + wn + nt * 8 + tg * 2;
            bv[nt][0] = bias[gc];
            bv[nt][1] = bias[gc + 1];
        }
#pragma unroll
        for (int mt = 0; mt < 4; mt++)
#pragma unroll
            for (int nt = 0; nt < 4; nt++) {
                int r0 = wm + mt * 16 + g;
                int cc = wn + nt * 8 + tg * 2;
                Cs[r0 * CPITCH + cc]       = acc[mt][nt][0] + bv[nt][0];
                Cs[r0 * CPITCH + cc + 1]   = acc[mt][nt][1] + bv[nt][1];
                Cs[(r0 + 8) * CPITCH + cc]     = acc[mt][nt][2] + bv[nt][0];
                Cs[(r0 + 8) * CPITCH + cc + 1] = acc[mt][nt][3] + bv[nt][1];
            }
        __syncthreads();

        const int b = m0 >> 11;
        const int sb0 = m0 & 2047;
        const int h0 = (n0 & 1023) >> 6;

        if (n0 < 2048) {
            // Q or K: [bh][s][64] row-major
            __nv_bfloat16* Dh = (n0 < 1024) ? g_Qh : g_Kh;
            __nv_bfloat16* Dl = (n0 < 1024) ? g_Ql : g_Kl;
            const int u = t & 63;
            const int h = h0 + (u >> 5);
            const int d0 = (u * 2) & 63;
            const int rofs = t >> 6;
#pragma unroll
            for (int p = 0; p < 32; p++) {
                int row = p * 4 + rofs;
                float v0 = Cs[row * CPITCH + 2 * u];
                float v1 = Cs[row * CPITCH + 2 * u + 1];
                uint32_t hh, ll;
                split2(v0, v1, hh, ll);
                size_t dst = ((size_t)(b * NHEADS + h) * SEQ + sb0 + row) * HD + d0;
                *(uint32_t*)(Dh + dst) = hh;
                *(uint32_t*)(Dl + dst) = ll;
            }
        } else {
            // V: transposed [bh][d][s]
            const int w = t >> 5;
            const int l = t & 31;
#pragma unroll
            for (int i = 0; i < 16; i++) {
                int c = w * 16 + i;
                int h = h0 + (c >> 6);
                int d = c & 63;
#pragma unroll
                for (int qq = 0; qq < 2; qq++) {
                    int r = 2 * (l + 32 * qq);
                    float v0 = Cs[r * CPITCH + c];
                    float v1 = Cs[(r + 1) * CPITCH + c];
                    uint32_t hh, ll;
                    split2(v0, v1, hh, ll);
                    size_t dst = ((size_t)(b * NHEADS + h) * HD + d) * SEQ + sb0 + r;
                    *(uint32_t*)(g_Vth + dst) = hh;
                    *(uint32_t*)(g_Vtl + dst) = ll;
                }
            }
        }
    }
}

// ---------------------------------------------------------------------------
// Tensor-core flash attention (bf16 hi/lo, 3-pass emulation both GEMMs).
// Grid (SEQ/64, NHEADS, BATCH), 128 threads (4 warps, 16 rows each).
// ---------------------------------------------------------------------------
#define APB 144
#define AARR (64 * APB)
#define ASTG (4 * AARR)
#define ATTN_SMEM (2 * AARR + 2 * ASTG)   /* 92160 */

__global__ void __launch_bounds__(128, 2) attn_tc(
    const __nv_bfloat16* __restrict__ Qh, const __nv_bfloat16* __restrict__ Ql,
    const __nv_bfloat16* __restrict__ Kh, const __nv_bfloat16* __restrict__ Kl,
    const __nv_bfloat16* __restrict__ Vth, const __nv_bfloat16* __restrict__ Vtl)
{
    extern __shared__ char dyn_smem[];
    const int t = threadIdx.x, wid = t >> 5, lane = t & 31;
    const int qt = blockIdx.x, h = blockIdx.y, b = blockIdx.z;
    const int bh = b * NHEADS + h;
    const int q0 = qt * 64;

    const uint32_t sQh = smem_u32(dyn_smem);
    const uint32_t sQl = sQh + AARR;
    const uint32_t sStg = sQl + AARR;

    const size_t qkBase = (size_t)bh * SEQ * HD;
    const size_t vBase  = (size_t)bh * HD * SEQ;

    {
#pragma unroll
        for (int i = 0; i < 8; i++) {
            int idx = t + i * 128;
            int arr = idx >> 9;
            int u = idx & 511, row = u >> 3, ch = u & 7;
            const __nv_bfloat16* src = (arr ? Ql : Qh) + qkBase + (size_t)(q0 + row) * HD + ch * 8;
            CP_ASYNC16(sQh + arr * AARR + row * APB + ch * 16, src);
        }
    }
#define LOAD_KV_STAGE(sbuf, kt0) do { \
    int kk0 = (kt0) * 64; \
    _Pragma("unroll") \
    for (int i = 0; i < 16; i++) { \
        int idx = t + i * 128; \
        int arr = idx >> 9; \
        int u = idx & 511, row = u >> 3, ch = u & 7; \
        const __nv_bfloat16* src; \
        if (arr == 0)      src = Kh  + qkBase + (size_t)(kk0 + row) * HD + ch * 8; \
        else if (arr == 1) src = Kl  + qkBase + (size_t)(kk0 + row) * HD + ch * 8; \
        else if (arr == 2) src = Vth + vBase + (size_t)row * SEQ + kk0 + ch * 8; \
        else               src = Vtl + vBase + (size_t)row * SEQ + kk0 + ch * 8; \
        CP_ASYNC16((sbuf) + arr * AARR + row * APB + ch * 16, src); \
    } \
} while (0)

    LOAD_KV_STAGE(sStg, 0);
    CP_COMMIT();
    LOAD_KV_STAGE(sStg + ASTG, 1);
    CP_COMMIT();

    const int wm = wid * 16;
    const int lmat = lane >> 3, lr = lane & 7;
    const uint32_t aOff = (uint32_t)((wm + (lmat & 1) * 8 + lr) * APB + (lmat >> 1) * 16);
    const uint32_t bOff = (uint32_t)(((lmat >> 1) * 8 + lr) * APB + (lmat & 1) * 16);
    const int g = lane >> 2, tg = lane & 3;

    float O[8][4];
#pragma unroll
    for (int i = 0; i < 8; i++)
#pragma unroll
        for (int j = 0; j < 4; j++) O[i][j] = 0.f;
    float m0r = -1e30f, m1r = -1e30f, l0 = 0.f, l1 = 0.f;

    const int NKT = SEQ / 64;
    for (int kt = 0; kt < NKT; kt++) {
        CP_WAIT1();
        __syncthreads();
        const uint32_t sb = sStg + (kt & 1) * ASTG;
        const uint32_t sKh = sb, sKl = sb + AARR, sVh = sb + 2 * AARR, sVl = sb + 3 * AARR;

        float S[8][4];
#pragma unroll
        for (int i = 0; i < 8; i++)
#pragma unroll
            for (int j = 0; j < 4; j++) S[i][j] = 0.f;

#pragma unroll
        for (int kc = 0; kc < 4; kc++) {
            uint32_t qh[4], ql[4];
            LDSM4(qh, sQh + aOff + kc * 32);
            LDSM4(ql, sQl + aOff + kc * 32);
#pragma unroll
            for (int j = 0; j < 4; j++) {
                uint32_t kh[4], kl[4];
                LDSM4(kh, sKh + j * (16 * APB) + bOff + kc * 32);
                LDSM4(kl, sKl + j * (16 * APB) + bOff + kc * 32);
                MMA16816(S[2 * j],     qh, kh[0], kh[1]);
                MMA16816(S[2 * j + 1], qh, kh[2], kh[3]);
                MMA16816(S[2 * j],     qh, kl[0], kl[1]);
                MMA16816(S[2 * j + 1], qh, kl[2], kl[3]);
                MMA16816(S[2 * j],     ql, kh[0], kh[1]);
                MMA16816(S[2 * j + 1], ql, kh[2], kh[3]);
            }
        }

        float rmax0 = -1e30f, rmax1 = -1e30f;
#pragma unroll
        for (int i = 0; i < 8; i++) {
            rmax0 = fmaxf(rmax0, fmaxf(S[i][0], S[i][1]));
            rmax1 = fmaxf(rmax1, fmaxf(S[i][2], S[i][3]));
        }
#pragma unroll
        for (int d = 1; d <= 2; d <<= 1) {
            rmax0 = fmaxf(rmax0, __shfl_xor_sync(0xffffffffu, rmax0, d));
            rmax1 = fmaxf(rmax1, __shfl_xor_sync(0xffffffffu, rmax1, d));
        }
        float mn0 = fmaxf(m0r, rmax0), mn1 = fmaxf(m1r, rmax1);
        float ms0 = mn0 * SC, ms1 = mn1 * SC;
        float sum0 = 0.f, sum1 = 0.f;
#pragma unroll
        for (int i = 0; i < 8; i++) {
            S[i][0] = ex2(fmaf(S[i][0], SC, -ms0));
            S[i][1] = ex2(fmaf(S[i][1], SC, -ms0));
            S[i][2] = ex2(fmaf(S[i][2], SC, -ms1));
            S[i][3] = ex2(fmaf(S[i][3], SC, -ms1));
            sum0 += S[i][0] + S[i][1];
            sum1 += S[i][2] + S[i][3];
        }
#pragma unroll
        for (int d = 1; d <= 2; d <<= 1) {
            sum0 += __shfl_xor_sync(0xffffffffu, sum0, d);
            sum1 += __shfl_xor_sync(0xffffffffu, sum1, d);
        }
        float c0 = ex2(SC * (m0r - mn0)), c1 = ex2(SC * (m1r - mn1));
        l0 = l0 * c0 + sum0;
        l1 = l1 * c1 + sum1;
        m0r = mn0; m1r = mn1;
#pragma unroll
        for (int i = 0; i < 8; i++) {
            O[i][0] *= c0; O[i][1] *= c0;
            O[i][2] *= c1; O[i][3] *= c1;
        }

#pragma unroll
        for (int kg = 0; kg < 4; kg++) {
            uint32_t ph[4], pl[4];
            split2(S[2 * kg][0],     S[2 * kg][1],     ph[0], pl[0]);
            split2(S[2 * kg][2],     S[2 * kg][3],     ph[1], pl[1]);
            split2(S[2 * kg + 1][0], S[2 * kg + 1][1], ph[2], pl[2]);
            split2(S[2 * kg + 1][2], S[2 * kg + 1][3], ph[3], pl[3]);
#pragma unroll
            for (int dn = 0; dn < 4; dn++) {
                uint32_t vh[4], vl[4];
                LDSM4(vh, sVh + dn * (16 * APB) + bOff + kg * 32);
                LDSM4(vl, sVl + dn * (16 * APB) + bOff + kg * 32);
                MMA16816(O[2 * dn],     ph, vh[0], vh[1]);
                MMA16816(O[2 * dn + 1], ph, vh[2], vh[3]);
                MMA16816(O[2 * dn],     ph, vl[0], vl[1]);
                MMA16816(O[2 * dn + 1], ph, vl[2], vl[3]);
                MMA16816(O[2 * dn],     pl, vh[0], vh[1]);
                MMA16816(O[2 * dn + 1], pl, vh[2], vh[3]);
            }
        }

        __syncthreads();
        if (kt + 2 < NKT) {
            LOAD_KV_STAGE(sStg + (kt & 1) * ASTG, kt + 2);
        }
        CP_COMMIT();
    }

    float inv0 = 1.0f / l0, inv1 = 1.0f / l1;
    int r0 = b * SEQ + q0 + wm + g;
    int r1 = r0 + 8;
#pragma unroll
    for (int ot = 0; ot < 8; ot++) {
        int col = h * HD + ot * 8 + tg * 2;
        uint32_t uh, ul;
        split2(O[ot][0] * inv0, O[ot][1] * inv0, uh, ul);
        *(uint32_t*)(g_ch + (size_t)r0 * DMODEL + col) = uh;
        *(uint32_t*)(g_cl + (size_t)r0 * DMODEL + col) = ul;
        split2(O[ot][2] * inv1, O[ot][3] * inv1, uh, ul);
        *(uint32_t*)(g_ch + (size_t)r1 * DMODEL + col) = uh;
        *(uint32_t*)(g_cl + (size_t)r1 * DMODEL + col) = ul;
    }
}

extern "C" void kernel_launch(void* const* d_in, const int* in_sizes, int n_in,
                              void* d_out, int out_size)
{
    const float* x     = (const float*)d_in[0];
    const float* qkv_w = (const float*)d_in[1];
    const float* qkv_b = (const float*)d_in[2];
    const float* out_w = (const float*)d_in[3];
    const float* out_b = (const float*)d_in[4];
    float* out = (float*)d_out;

    void *p_xh, *p_xl, *p_qwh, *p_qwl, *p_owh, *p_owl, *p_ch, *p_cl;
    void *p_Qh, *p_Ql, *p_Kh, *p_Kl, *p_Vth, *p_Vtl;
    cudaGetSymbolAddress(&p_xh, g_xh);   cudaGetSymbolAddress(&p_xl, g_xl);
    cudaGetSymbolAddress(&p_qwh, g_qwh); cudaGetSymbolAddress(&p_qwl, g_qwl);
    cudaGetSymbolAddress(&p_owh, g_owh); cudaGetSymbolAddress(&p_owl, g_owl);
    cudaGetSymbolAddress(&p_ch, g_ch);   cudaGetSymbolAddress(&p_cl, g_cl);
    cudaGetSymbolAddress(&p_Qh, g_Qh);   cudaGetSymbolAddress(&p_Ql, g_Ql);
    cudaGetSymbolAddress(&p_Kh, g_Kh);   cudaGetSymbolAddress(&p_Kl, g_Kl);
    cudaGetSymbolAddress(&p_Vth, g_Vth); cudaGetSymbolAddress(&p_Vtl, g_Vtl);

    cudaFuncSetAttribute(gemm_tc<false>, cudaFuncAttributeMaxDynamicSharedMemorySize,
                         GEMM_SMEM);
    cudaFuncSetAttribute(gemm_tc<true>, cudaFuncAttributeMaxDynamicSharedMemorySize,
                         GEMM_SMEM);
    cudaFuncSetAttribute(attn_tc, cudaFuncAttributeMaxDynamicSharedMemorySize,
                         ATTN_SMEM);

    // split weights/x to bf16 hi/lo
    {
        int n4 = ROWS * DMODEL / 4;
        split_kernel<<<(n4 + 255) / 256, 256>>>((const float4*)x, (uint2*)p_xh, (uint2*)p_xl, n4);
        n4 = NQKV * DMODEL / 4;
        split_kernel<<<(n4 + 255) / 256, 256>>>((const float4*)qkv_w, (uint2*)p_qwh, (uint2*)p_qwl, n4);
        n4 = DMODEL * DMODEL / 4;
        split_kernel<<<(n4 + 255) / 256, 256>>>((const float4*)out_w, (uint2*)p_owh, (uint2*)p_owl, n4);
    }

    // 1) QKV projection with fused per-head split/transpose epilogue
    gemm_tc<true><<<dim3(NQKV / 128, ROWS / 128), 256, GEMM_SMEM>>>(
        (const __nv_bfloat16*)p_xh, (const __nv_bfloat16*)p_xl,
        (const __nv_bfloat16*)p_qwh, (const __nv_bfloat16*)p_qwl,
        qkv_b, nullptr, NQKV, DMODEL);

    // 2) tensor-core flash attention -> ctx (bf16 hi/lo)
    attn_tc<<<dim3(SEQ / 64, NHEADS, BATCH), 128, ATTN_SMEM>>>(
        (const __nv_bfloat16*)p_Qh, (const __nv_bfloat16*)p_Ql,
        (const __nv_bfloat16*)p_Kh, (const __nv_bfloat16*)p_Kl,
        (const __nv_bfloat16*)p_Vth, (const __nv_bfloat16*)p_Vtl);

    // 3) output projection
    gemm_tc<false><<<dim3(DMODEL / 128, ROWS / 128), 256, GEMM_SMEM>>>(
        (const __nv_bfloat16*)p_ch, (const __nv_bfloat16*)p_cl,
        (const __nv_bfloat16*)p_owh, (const __nv_bfloat16*)p_owl,
        out_b, out, DMODEL, DMODEL);
}

// round 7
// speedup vs baseline: 4.2062x; 1.3873x over previous
#include <cuda_runtime.h>
#include <cuda_fp16.h>
#include <cstdint>
#include <math.h>

#define DMODEL 1024
#define NHEADS 16
#define HD 64
#define BATCH 4
#define SEQ 2048
#define ROWS (BATCH * SEQ)   /* 8192 */
#define NQKV (3 * DMODEL)    /* 3072 */

// softmax scale folded with log2(e) (base-2 softmax)
#define SC (0.125f * 1.44269504088896340736f)

// ---------------------------------------------------------------------------
// Scratch (allocation-free __device__ globals), fp16 operands
// ---------------------------------------------------------------------------
__device__ __align__(256) __half g_xh[(size_t)ROWS * DMODEL];        // x (A side, hi only)
__device__ __align__(256) __half g_qwh[(size_t)NQKV * DMODEL];       // qkv_w hi
__device__ __align__(256) __half g_qwl[(size_t)NQKV * DMODEL];       // qkv_w lo
__device__ __align__(256) __half g_owh[(size_t)DMODEL * DMODEL];     // out_w hi
__device__ __align__(256) __half g_owl[(size_t)DMODEL * DMODEL];     // out_w lo
__device__ __align__(256) __half g_ch[(size_t)ROWS * DMODEL];        // ctx (A side, hi only)
// per-head attention operands, written by fused QKV epilogue
__device__ __align__(256) __half g_Qh[(size_t)ROWS * DMODEL];        // Q hi only (A side)
__device__ __align__(256) __half g_Kh[(size_t)ROWS * DMODEL];        // K hi
__device__ __align__(256) __half g_Kl[(size_t)ROWS * DMODEL];        // K lo
__device__ __align__(256) __half g_Vth[(size_t)ROWS * DMODEL];       // V^T hi [bh][d][s]
__device__ __align__(256) __half g_Vtl[(size_t)ROWS * DMODEL];       // V^T lo

// ---------------------------------------------------------------------------
// helpers
// ---------------------------------------------------------------------------
__device__ __forceinline__ uint32_t smem_u32(const void* p) {
    return (uint32_t)__cvta_generic_to_shared(p);
}

__device__ __forceinline__ uint32_t pack2(float a, float b) {
    __half2 h = __floats2half2_rn(a, b);
    return *reinterpret_cast<uint32_t*>(&h);
}

__device__ __forceinline__ void split2(float a, float b, uint32_t& h, uint32_t& l) {
    __half ha = __float2half_rn(a), hb = __float2half_rn(b);
    float ra = a - __half2float(ha), rb = b - __half2float(hb);
    __half2 hh = __halves2half2(ha, hb);
    h = *reinterpret_cast<uint32_t*>(&hh);
    l = pack2(ra, rb);
}

__device__ __forceinline__ float ex2(float x) {
    float y;
    asm("ex2.approx.ftz.f32 %0, %1;" : "=f"(y) : "f"(x));
    return y;
}

#define LDSM4(r, addr) \
    asm volatile("ldmatrix.sync.aligned.m8n8.x4.shared.b16 {%0,%1,%2,%3}, [%4];" \
                 : "=r"((r)[0]), "=r"((r)[1]), "=r"((r)[2]), "=r"((r)[3]) : "r"(addr))

#define MMA16816(d, a, b0, b1) \
    asm volatile("mma.sync.aligned.m16n8k16.row.col.f32.f16.f16.f32 " \
                 "{%0,%1,%2,%3}, {%4,%5,%6,%7}, {%8,%9}, {%0,%1,%2,%3};" \
                 : "+f"((d)[0]), "+f"((d)[1]), "+f"((d)[2]), "+f"((d)[3]) \
                 : "r"((a)[0]), "r"((a)[1]), "r"((a)[2]), "r"((a)[3]), \
                   "r"(b0), "r"(b1))

#define CP_ASYNC16(dst, src) \
    asm volatile("cp.async.cg.shared.global [%0], [%1], 16;" :: "r"(dst), "l"(src))
#define CP_COMMIT() asm volatile("cp.async.commit_group;" ::: "memory")
#define CP_WAIT1()  asm volatile("cp.async.wait_group 1;" ::: "memory")
#define CP_WAIT0()  asm volatile("cp.async.wait_group 0;" ::: "memory")

// ---------------------------------------------------------------------------
// fp32 -> fp16 hi/lo split (weights, B side)
// ---------------------------------------------------------------------------
__global__ void split_kernel(const float4* __restrict__ in, uint2* __restrict__ hi,
                             uint2* __restrict__ lo, int n4) {
    int i = blockIdx.x * blockDim.x + threadIdx.x;
    if (i >= n4) return;
    float4 v = in[i];
    uint2 uh, ul;
    split2(v.x, v.y, uh.x, ul.x);
    split2(v.z, v.w, uh.y, ul.y);
    hi[i] = uh;
    lo[i] = ul;
}

// fp32 -> fp16 convert only (activations, A side)
__global__ void cvt_kernel(const float4* __restrict__ in, uint2* __restrict__ hi, int n4) {
    int i = blockIdx.x * blockDim.x + threadIdx.x;
    if (i >= n4) return;
    float4 v = in[i];
    uint2 uh;
    uh.x = pack2(v.x, v.y);
    uh.y = pack2(v.z, v.w);
    hi[i] = uh;
}

// ---------------------------------------------------------------------------
// Tensor-core GEMM via mma.sync fp16 2-pass emulation:
// C = Ah*(Bh + Bl)^T + bias,  A in fp16 (hi only), B split hi/lo.
// BM=BN=128, BK=32, 256 thr, warp tile 64x32, 3-stage cp.async, 2 CTAs/SM.
// QKV_EPI: write Q(hi) / K(hi+lo) per-head and V transposed (hi+lo).
// ---------------------------------------------------------------------------
#define BK 32
#define PITCHB 80
#define ARR_BYTES (128 * PITCHB)        /* 10240 */
#define STG_BYTES (3 * ARR_BYTES)       /* 30720: Ah, Bh, Bl */
#define GEMM_SMEM (3 * STG_BYTES)       /* 92160 (>= 67584 epilogue staging) */
#define CPITCH 132                      /* C staging pitch (floats) */

__device__ __forceinline__ void load_stage(
    uint32_t sb, int k0, int t,
    const __half* __restrict__ Ah,
    const __half* __restrict__ Bh, const __half* __restrict__ Bl,
    int m0, int n0, int K)
{
#pragma unroll
    for (int i = 0; i < 6; i++) {
        int idx = t + i * 256;          // 0..1535
        int arr = idx >> 9;             // 0:Ah 1:Bh 2:Bl
        int u   = idx & 511;
        int row = u & 127;
        int c   = u >> 7;               // 16B chunk 0..3
        const __half* base = (arr == 0) ? Ah : (arr == 1) ? Bh : Bl;
        int grow = ((arr == 0) ? m0 : n0) + row;
        const __half* src = base + (size_t)grow * K + k0 + c * 8;
        uint32_t dst = sb + arr * ARR_BYTES + row * PITCHB + c * 16;
        CP_ASYNC16(dst, src);
    }
}

template <bool QKV_EPI>
__global__ void __launch_bounds__(256, 2) gemm_tc(
    const __half* __restrict__ Ah,
    const __half* __restrict__ Bh, const __half* __restrict__ Bl,
    const float* __restrict__ bias, float* __restrict__ C, int N, int K)
{
    extern __shared__ char dyn_smem[];
    const int t = threadIdx.x, wid = t >> 5, lane = t & 31;
    const int m0 = blockIdx.y * 128, n0 = blockIdx.x * 128;
    const int KT = K / BK;

    const uint32_t sbase = smem_u32(dyn_smem);
    const int wm = (wid >> 2) * 64;
    const int wn = (wid & 3) * 32;

    const int lmat = lane >> 3, lr = lane & 7;
    const uint32_t aOff = (uint32_t)((wm + (lmat & 1) * 8 + lr) * PITCHB + (lmat >> 1) * 16);
    const uint32_t bOff = (uint32_t)((wn + (lmat >> 1) * 8 + lr) * PITCHB + (lmat & 1) * 16);

    float acc[4][4][4];
#pragma unroll
    for (int i = 0; i < 4; i++)
#pragma unroll
        for (int j = 0; j < 4; j++)
#pragma unroll
            for (int r = 0; r < 4; r++) acc[i][j][r] = 0.f;

    load_stage(sbase + 0 * STG_BYTES, 0,  t, Ah, Bh, Bl, m0, n0, K);
    CP_COMMIT();
    load_stage(sbase + 1 * STG_BYTES, BK, t, Ah, Bh, Bl, m0, n0, K);
    CP_COMMIT();

    for (int kt = 0; kt < KT; kt++) {
        CP_WAIT1();
        __syncthreads();
        if (kt + 2 < KT)
            load_stage(sbase + ((kt + 2) % 3) * STG_BYTES, (kt + 2) * BK,
                       t, Ah, Bh, Bl, m0, n0, K);
        CP_COMMIT();

        const uint32_t sb = sbase + (kt % 3) * STG_BYTES;
#pragma unroll
        for (int ks = 0; ks < 2; ks++) {
            uint32_t ah[4][4], bh[2][4], bl[2][4];
            const uint32_t kb = ks * 32;
#pragma unroll
            for (int mt = 0; mt < 4; mt++)
                LDSM4(ah[mt], sb + 0 * ARR_BYTES + aOff + mt * (16 * PITCHB) + kb);
#pragma unroll
            for (int j = 0; j < 2; j++) {
                LDSM4(bh[j], sb + 1 * ARR_BYTES + bOff + j * (16 * PITCHB) + kb);
                LDSM4(bl[j], sb + 2 * ARR_BYTES + bOff + j * (16 * PITCHB) + kb);
            }
#pragma unroll
            for (int mt = 0; mt < 4; mt++)
#pragma unroll
                for (int nt = 0; nt < 4; nt++)
                    MMA16816(acc[mt][nt], ah[mt],
                             bh[nt >> 1][(nt & 1) * 2], bh[nt >> 1][(nt & 1) * 2 + 1]);
#pragma unroll
            for (int mt = 0; mt < 4; mt++)
#pragma unroll
                for (int nt = 0; nt < 4; nt++)
                    MMA16816(acc[mt][nt], ah[mt],
                             bl[nt >> 1][(nt & 1) * 2], bl[nt >> 1][(nt & 1) * 2 + 1]);
        }
    }
    CP_WAIT0();
    __syncthreads();

    const int g = lane >> 2, tg = lane & 3;

    if (!QKV_EPI) {
        float* Cs = (float*)dyn_smem;      // [128][CPITCH]
#pragma unroll
        for (int mt = 0; mt < 4; mt++)
#pragma unroll
            for (int nt = 0; nt < 4; nt++) {
                int r0 = wm + mt * 16 + g;
                int cc = wn + nt * 8 + tg * 2;
                Cs[r0 * CPITCH + cc]       = acc[mt][nt][0];
                Cs[r0 * CPITCH + cc + 1]   = acc[mt][nt][1];
                Cs[(r0 + 8) * CPITCH + cc]     = acc[mt][nt][2];
                Cs[(r0 + 8) * CPITCH + cc + 1] = acc[mt][nt][3];
            }
        __syncthreads();

        const int q = t & 31;
        const int rb = t >> 5;
        float4 bv = *(const float4*)(bias + n0 + q * 4);
#pragma unroll
        for (int i = 0; i < 16; i++) {
            int row = rb + i * 8;
            float4 v = *(const float4*)&Cs[row * CPITCH + q * 4];
            v.x += bv.x; v.y += bv.y; v.z += bv.z; v.w += bv.w;
            *(float4*)(C + (size_t)(m0 + row) * N + n0 + q * 4) = v;
        }
    } else {
        // fused QKV epilogue: bias + fp16 split + per-head scatter
        float* Cs = (float*)dyn_smem;      // [128][CPITCH]
        float bv[4][2];
#pragma unroll
        for (int nt = 0; nt < 4; nt++) {
            int gc = n0 + wn + nt * 8 + tg * 2;
            bv[nt][0] = bias[gc];
            bv[nt][1] = bias[gc + 1];
        }
#pragma unroll
        for (int mt = 0; mt < 4; mt++)
#pragma unroll
            for (int nt = 0; nt < 4; nt++) {
                int r0 = wm + mt * 16 + g;
                int cc = wn + nt * 8 + tg * 2;
                Cs[r0 * CPITCH + cc]       = acc[mt][nt][0] + bv[nt][0];
                Cs[r0 * CPITCH + cc + 1]   = acc[mt][nt][1] + bv[nt][1];
                Cs[(r0 + 8) * CPITCH + cc]     = acc[mt][nt][2] + bv[nt][0];
                Cs[(r0 + 8) * CPITCH + cc + 1] = acc[mt][nt][3] + bv[nt][1];
            }
        __syncthreads();

        const int b = m0 >> 11;
        const int sb0 = m0 & 2047;
        const int h0 = (n0 & 1023) >> 6;

        if (n0 < 2048) {
            // Q (hi only) or K (hi+lo): [bh][s][64] row-major
            const bool isQ = (n0 < 1024);
            __half* Dh = isQ ? g_Qh : g_Kh;
            const int u = t & 63;
            const int h = h0 + (u >> 5);
            const int d0 = (u * 2) & 63;
            const int rofs = t >> 6;
#pragma unroll
            for (int p = 0; p < 32; p++) {
                int row = p * 4 + rofs;
                float v0 = Cs[row * CPITCH + 2 * u];
                float v1 = Cs[row * CPITCH + 2 * u + 1];
                size_t dst = ((size_t)(b * NHEADS + h) * SEQ + sb0 + row) * HD + d0;
                if (isQ) {
                    *(uint32_t*)(Dh + dst) = pack2(v0, v1);
                } else {
                    uint32_t hh, ll;
                    split2(v0, v1, hh, ll);
                    *(uint32_t*)(Dh + dst) = hh;
                    *(uint32_t*)(g_Kl + dst) = ll;
                }
            }
        } else {
            // V: transposed [bh][d][s], hi+lo
            const int w = t >> 5;
            const int l = t & 31;
#pragma unroll
            for (int i = 0; i < 16; i++) {
                int c = w * 16 + i;
                int h = h0 + (c >> 6);
                int d = c & 63;
#pragma unroll
                for (int qq = 0; qq < 2; qq++) {
                    int r = 2 * (l + 32 * qq);
                    float v0 = Cs[r * CPITCH + c];
                    float v1 = Cs[(r + 1) * CPITCH + c];
                    uint32_t hh, ll;
                    split2(v0, v1, hh, ll);
                    size_t dst = ((size_t)(b * NHEADS + h) * HD + d) * SEQ + sb0 + r;
                    *(uint32_t*)(g_Vth + dst) = hh;
                    *(uint32_t*)(g_Vtl + dst) = ll;
                }
            }
        }
    }
}

// ---------------------------------------------------------------------------
// Tensor-core flash attention, fp16 2-pass emulation:
// S = Qh*(Kh+Kl)^T ; O += P*(Vh+Vl) with P in fp16 (hi only).
// Grid (SEQ/64, NHEADS, BATCH), 128 threads (4 warps, 16 rows each).
// ---------------------------------------------------------------------------
#define APB 144
#define AARR (64 * APB)                 /* 9216 */
#define ASTG (4 * AARR)                 /* 36864: Kh,Kl,Vh,Vl */
#define ATTN_SMEM (AARR + 2 * ASTG)     /* 82944 */

__global__ void __launch_bounds__(128, 2) attn_tc(
    const __half* __restrict__ Qh,
    const __half* __restrict__ Kh, const __half* __restrict__ Kl,
    const __half* __restrict__ Vth, const __half* __restrict__ Vtl)
{
    extern __shared__ char dyn_smem[];
    const int t = threadIdx.x, wid = t >> 5, lane = t & 31;
    const int qt = blockIdx.x, h = blockIdx.y, b = blockIdx.z;
    const int bh = b * NHEADS + h;
    const int q0 = qt * 64;

    const uint32_t sQh = smem_u32(dyn_smem);
    const uint32_t sStg = sQh + AARR;

    const size_t qkBase = (size_t)bh * SEQ * HD;
    const size_t vBase  = (size_t)bh * HD * SEQ;

    // Q tile (hi only)
#pragma unroll
    for (int i = 0; i < 4; i++) {
        int idx = t + i * 128;          // 0..511
        int row = idx >> 3, ch = idx & 7;
        const __half* src = Qh + qkBase + (size_t)(q0 + row) * HD + ch * 8;
        CP_ASYNC16(sQh + row * APB + ch * 16, src);
    }
#define LOAD_KV_STAGE(sbuf, kt0) do { \
    int kk0 = (kt0) * 64; \
    _Pragma("unroll") \
    for (int i = 0; i < 16; i++) { \
        int idx = t + i * 128; \
        int arr = idx >> 9; \
        int u = idx & 511, row = u >> 3, ch = u & 7; \
        const __half* src; \
        if (arr == 0)      src = Kh  + qkBase + (size_t)(kk0 + row) * HD + ch * 8; \
        else if (arr == 1) src = Kl  + qkBase + (size_t)(kk0 + row) * HD + ch * 8; \
        else if (arr == 2) src = Vth + vBase + (size_t)row * SEQ + kk0 + ch * 8; \
        else               src = Vtl + vBase + (size_t)row * SEQ + kk0 + ch * 8; \
        CP_ASYNC16((sbuf) + arr * AARR + row * APB + ch * 16, src); \
    } \
} while (0)

    LOAD_KV_STAGE(sStg, 0);
    CP_COMMIT();
    LOAD_KV_STAGE(sStg + ASTG, 1);
    CP_COMMIT();

    const int wm = wid * 16;
    const int lmat = lane >> 3, lr = lane & 7;
    const uint32_t aOff = (uint32_t)((wm + (lmat & 1) * 8 + lr) * APB + (lmat >> 1) * 16);
    const uint32_t bOff = (uint32_t)(((lmat >> 1) * 8 + lr) * APB + (lmat & 1) * 16);
    const int g = lane >> 2, tg = lane & 3;

    float O[8][4];
#pragma unroll
    for (int i = 0; i < 8; i++)
#pragma unroll
        for (int j = 0; j < 4; j++) O[i][j] = 0.f;
    float m0r = -1e30f, m1r = -1e30f, l0 = 0.f, l1 = 0.f;

    const int NKT = SEQ / 64;
    for (int kt = 0; kt < NKT; kt++) {
        CP_WAIT1();
        __syncthreads();
        const uint32_t sb = sStg + (kt & 1) * ASTG;
        const uint32_t sKh = sb, sKl = sb + AARR, sVh = sb + 2 * AARR, sVl = sb + 3 * AARR;

        float S[8][4];
#pragma unroll
        for (int i = 0; i < 8; i++)
#pragma unroll
            for (int j = 0; j < 4; j++) S[i][j] = 0.f;

#pragma unroll
        for (int kc = 0; kc < 4; kc++) {
            uint32_t qh[4];
            LDSM4(qh, sQh + aOff + kc * 32);
#pragma unroll
            for (int j = 0; j < 4; j++) {
                uint32_t kh[4], kl[4];
                LDSM4(kh, sKh + j * (16 * APB) + bOff + kc * 32);
                LDSM4(kl, sKl + j * (16 * APB) + bOff + kc * 32);
                MMA16816(S[2 * j],     qh, kh[0], kh[1]);
                MMA16816(S[2 * j + 1], qh, kh[2], kh[3]);
                MMA16816(S[2 * j],     qh, kl[0], kl[1]);
                MMA16816(S[2 * j + 1], qh, kl[2], kl[3]);
            }
        }

        float rmax0 = -1e30f, rmax1 = -1e30f;
#pragma unroll
        for (int i = 0; i < 8; i++) {
            rmax0 = fmaxf(rmax0, fmaxf(S[i][0], S[i][1]));
            rmax1 = fmaxf(rmax1, fmaxf(S[i][2], S[i][3]));
        }
#pragma unroll
        for (int d = 1; d <= 2; d <<= 1) {
            rmax0 = fmaxf(rmax0, __shfl_xor_sync(0xffffffffu, rmax0, d));
            rmax1 = fmaxf(rmax1, __shfl_xor_sync(0xffffffffu, rmax1, d));
        }
        float mn0 = fmaxf(m0r, rmax0), mn1 = fmaxf(m1r, rmax1);
        float ms0 = mn0 * SC, ms1 = mn1 * SC;
        float sum0 = 0.f, sum1 = 0.f;
#pragma unroll
        for (int i = 0; i < 8; i++) {
            S[i][0] = ex2(fmaf(S[i][0], SC, -ms0));
            S[i][1] = ex2(fmaf(S[i][1], SC, -ms0));
            S[i][2] = ex2(fmaf(S[i][2], SC, -ms1));
            S[i][3] = ex2(fmaf(S[i][3], SC, -ms1));
            sum0 += S[i][0] + S[i][1];
            sum1 += S[i][2] + S[i][3];
        }
#pragma unroll
        for (int d = 1; d <= 2; d <<= 1) {
            sum0 += __shfl_xor_sync(0xffffffffu, sum0, d);
            sum1 += __shfl_xor_sync(0xffffffffu, sum1, d);
        }
        float c0 = ex2(SC * (m0r - mn0)), c1 = ex2(SC * (m1r - mn1));
        l0 = l0 * c0 + sum0;
        l1 = l1 * c1 + sum1;
        m0r = mn0; m1r = mn1;
#pragma unroll
        for (int i = 0; i < 8; i++) {
            O[i][0] *= c0; O[i][1] *= c0;
            O[i][2] *= c1; O[i][3] *= c1;
        }

#pragma unroll
        for (int kg = 0; kg < 4; kg++) {
            uint32_t ph[4];
            ph[0] = pack2(S[2 * kg][0],     S[2 * kg][1]);
            ph[1] = pack2(S[2 * kg][2],     S[2 * kg][3]);
            ph[2] = pack2(S[2 * kg + 1][0], S[2 * kg + 1][1]);
            ph[3] = pack2(S[2 * kg + 1][2], S[2 * kg + 1][3]);
#pragma unroll
            for (int dn = 0; dn < 4; dn++) {
                uint32_t vh[4], vl[4];
                LDSM4(vh, sVh + dn * (16 * APB) + bOff + kg * 32);
                LDSM4(vl, sVl + dn * (16 * APB) + bOff + kg * 32);
                MMA16816(O[2 * dn],     ph, vh[0], vh[1]);
                MMA16816(O[2 * dn + 1], ph, vh[2], vh[3]);
                MMA16816(O[2 * dn],     ph, vl[0], vl[1]);
                MMA16816(O[2 * dn + 1], ph, vl[2], vl[3]);
            }
        }

        __syncthreads();
        if (kt + 2 < NKT) {
            LOAD_KV_STAGE(sStg + (kt & 1) * ASTG, kt + 2);
        }
        CP_COMMIT();
    }

    float inv0 = 1.0f / l0, inv1 = 1.0f / l1;
    int r0 = b * SEQ + q0 + wm + g;
    int r1 = r0 + 8;
#pragma unroll
    for (int ot = 0; ot < 8; ot++) {
        int col = h * HD + ot * 8 + tg * 2;
        *(uint32_t*)(g_ch + (size_t)r0 * DMODEL + col) =
            pack2(O[ot][0] * inv0, O[ot][1] * inv0);
        *(uint32_t*)(g_ch + (size_t)r1 * DMODEL + col) =
            pack2(O[ot][2] * inv1, O[ot][3] * inv1);
    }
}

extern "C" void kernel_launch(void* const* d_in, const int* in_sizes, int n_in,
                              void* d_out, int out_size)
{
    const float* x     = (const float*)d_in[0];
    const float* qkv_w = (const float*)d_in[1];
    const float* qkv_b = (const float*)d_in[2];
    const float* out_w = (const float*)d_in[3];
    const float* out_b = (const float*)d_in[4];
    float* out = (float*)d_out;

    void *p_xh, *p_qwh, *p_qwl, *p_owh, *p_owl, *p_ch;
    void *p_Qh, *p_Kh, *p_Kl, *p_Vth, *p_Vtl;
    cudaGetSymbolAddress(&p_xh, g_xh);
    cudaGetSymbolAddress(&p_qwh, g_qwh); cudaGetSymbolAddress(&p_qwl, g_qwl);
    cudaGetSymbolAddress(&p_owh, g_owh); cudaGetSymbolAddress(&p_owl, g_owl);
    cudaGetSymbolAddress(&p_ch, g_ch);
    cudaGetSymbolAddress(&p_Qh, g_Qh);
    cudaGetSymbolAddress(&p_Kh, g_Kh);   cudaGetSymbolAddress(&p_Kl, g_Kl);
    cudaGetSymbolAddress(&p_Vth, g_Vth); cudaGetSymbolAddress(&p_Vtl, g_Vtl);

    cudaFuncSetAttribute(gemm_tc<false>, cudaFuncAttributeMaxDynamicSharedMemorySize,
                         GEMM_SMEM);
    cudaFuncSetAttribute(gemm_tc<true>, cudaFuncAttributeMaxDynamicSharedMemorySize,
                         GEMM_SMEM);
    cudaFuncSetAttribute(attn_tc, cudaFuncAttributeMaxDynamicSharedMemorySize,
                         ATTN_SMEM);

    // x -> fp16 (hi only); weights -> fp16 hi/lo
    {
        int n4 = ROWS * DMODEL / 4;
        cvt_kernel<<<(n4 + 255) / 256, 256>>>((const float4*)x, (uint2*)p_xh, n4);
        n4 = NQKV * DMODEL / 4;
        split_kernel<<<(n4 + 255) / 256, 256>>>((const float4*)qkv_w, (uint2*)p_qwh, (uint2*)p_qwl, n4);
        n4 = DMODEL * DMODEL / 4;
        split_kernel<<<(n4 + 255) / 256, 256>>>((const float4*)out_w, (uint2*)p_owh, (uint2*)p_owl, n4);
    }

    // 1) QKV projection with fused per-head split/transpose epilogue
    gemm_tc<true><<<dim3(NQKV / 128, ROWS / 128), 256, GEMM_SMEM>>>(
        (const __half*)p_xh,
        (const __half*)p_qwh, (const __half*)p_qwl,
        qkv_b, nullptr, NQKV, DMODEL);

    // 2) tensor-core flash attention -> ctx (fp16)
    attn_tc<<<dim3(SEQ / 64, NHEADS, BATCH), 128, ATTN_SMEM>>>(
        (const __half*)p_Qh,
        (const __half*)p_Kh, (const __half*)p_Kl,
        (const __half*)p_Vth, (const __half*)p_Vtl);

    // 3) output projection
    gemm_tc<false><<<dim3(DMODEL / 128, ROWS / 128), 256, GEMM_SMEM>>>(
        (const __half*)p_ch,
        (const __half*)p_owh, (const __half*)p_owl,
        out_b, out, DMODEL, DMODEL);
}

// round 8
// speedup vs baseline: 7.3191x; 1.7401x over previous
#include <cuda_runtime.h>
#include <cuda_fp16.h>
#include <cstdint>
#include <math.h>

#define DMODEL 1024
#define NHEADS 16
#define HD 64
#define BATCH 4
#define SEQ 2048
#define ROWS (BATCH * SEQ)   /* 8192 */
#define NQKV (3 * DMODEL)    /* 3072 */

// softmax scale folded with log2(e) (base-2 softmax)
#define SC (0.125f * 1.44269504088896340736f)

// ---------------------------------------------------------------------------
// Scratch (allocation-free __device__ globals), fp16 operands (hi only)
// ---------------------------------------------------------------------------
__device__ __align__(256) __half g_xh[(size_t)ROWS * DMODEL];        // x
__device__ __align__(256) __half g_qwh[(size_t)NQKV * DMODEL];       // qkv_w
__device__ __align__(256) __half g_owh[(size_t)DMODEL * DMODEL];     // out_w
__device__ __align__(256) __half g_ch[(size_t)ROWS * DMODEL];        // ctx
// per-head attention operands, written by fused QKV epilogue
__device__ __align__(256) __half g_Qh[(size_t)ROWS * DMODEL];        // Q [bh][s][64]
__device__ __align__(256) __half g_Kh[(size_t)ROWS * DMODEL];        // K [bh][s][64]
__device__ __align__(256) __half g_Vth[(size_t)ROWS * DMODEL];       // V^T [bh][d][s]

// ---------------------------------------------------------------------------
// helpers
// ---------------------------------------------------------------------------
__device__ __forceinline__ uint32_t smem_u32(const void* p) {
    return (uint32_t)__cvta_generic_to_shared(p);
}

__device__ __forceinline__ uint32_t pack2(float a, float b) {
    __half2 h = __floats2half2_rn(a, b);
    return *reinterpret_cast<uint32_t*>(&h);
}

__device__ __forceinline__ float ex2(float x) {
    float y;
    asm("ex2.approx.ftz.f32 %0, %1;" : "=f"(y) : "f"(x));
    return y;
}

#define LDSM4(r, addr) \
    asm volatile("ldmatrix.sync.aligned.m8n8.x4.shared.b16 {%0,%1,%2,%3}, [%4];" \
                 : "=r"((r)[0]), "=r"((r)[1]), "=r"((r)[2]), "=r"((r)[3]) : "r"(addr))

#define MMA16816(d, a, b0, b1) \
    asm volatile("mma.sync.aligned.m16n8k16.row.col.f32.f16.f16.f32 " \
                 "{%0,%1,%2,%3}, {%4,%5,%6,%7}, {%8,%9}, {%0,%1,%2,%3};" \
                 : "+f"((d)[0]), "+f"((d)[1]), "+f"((d)[2]), "+f"((d)[3]) \
                 : "r"((a)[0]), "r"((a)[1]), "r"((a)[2]), "r"((a)[3]), \
                   "r"(b0), "r"(b1))

#define CP_ASYNC16(dst, src) \
    asm volatile("cp.async.cg.shared.global [%0], [%1], 16;" :: "r"(dst), "l"(src))
#define CP_COMMIT() asm volatile("cp.async.commit_group;" ::: "memory")
#define CP_WAIT1()  asm volatile("cp.async.wait_group 1;" ::: "memory")
#define CP_WAIT0()  asm volatile("cp.async.wait_group 0;" ::: "memory")

// ---------------------------------------------------------------------------
// fp32 -> fp16 convert (4-wide)
// ---------------------------------------------------------------------------
__global__ void cvt_kernel(const float4* __restrict__ in, uint2* __restrict__ hi, int n4) {
    int i = blockIdx.x * blockDim.x + threadIdx.x;
    if (i >= n4) return;
    float4 v = in[i];
    uint2 uh;
    uh.x = pack2(v.x, v.y);
    uh.y = pack2(v.z, v.w);
    hi[i] = uh;
}

// ---------------------------------------------------------------------------
// Tensor-core GEMM via mma.sync, pure fp16 operands, fp32 accumulate.
// C = A*B^T + bias.  BM=BN=128, BK=32, 256 thr, warp tile 64x32,
// 3-stage cp.async pipeline, 2 CTAs/SM.
// QKV_EPI: write Q/K per-head fp16 and V transposed fp16.
// ---------------------------------------------------------------------------
#define BK 32
#define PITCHB 80
#define ARR_BYTES (128 * PITCHB)        /* 10240 */
#define STG_BYTES (2 * ARR_BYTES)       /* 20480: A, B */
#define GEMM_SMEM 67584                 /* max(3*STG=61440, epilogue 128*132*4) */
#define CPITCH 132                      /* C staging pitch (floats) */

__device__ __forceinline__ void load_stage(
    uint32_t sb, int k0, int t,
    const __half* __restrict__ A, const __half* __restrict__ B,
    int m0, int n0, int K)
{
#pragma unroll
    for (int i = 0; i < 4; i++) {
        int idx = t + i * 256;          // 0..1023
        int arr = idx >> 9;             // 0:A 1:B
        int u   = idx & 511;
        int row = u & 127;
        int c   = u >> 7;               // 16B chunk 0..3
        const __half* base = arr ? B : A;
        int grow = (arr ? n0 : m0) + row;
        const __half* src = base + (size_t)grow * K + k0 + c * 8;
        uint32_t dst = sb + arr * ARR_BYTES + row * PITCHB + c * 16;
        CP_ASYNC16(dst, src);
    }
}

template <bool QKV_EPI>
__global__ void __launch_bounds__(256, 2) gemm_tc(
    const __half* __restrict__ A, const __half* __restrict__ B,
    const float* __restrict__ bias, float* __restrict__ C, int N, int K)
{
    extern __shared__ char dyn_smem[];
    const int t = threadIdx.x, wid = t >> 5, lane = t & 31;
    const int m0 = blockIdx.y * 128, n0 = blockIdx.x * 128;
    const int KT = K / BK;

    const uint32_t sbase = smem_u32(dyn_smem);
    const int wm = (wid >> 2) * 64;
    const int wn = (wid & 3) * 32;

    const int lmat = lane >> 3, lr = lane & 7;
    const uint32_t aOff = (uint32_t)((wm + (lmat & 1) * 8 + lr) * PITCHB + (lmat >> 1) * 16);
    const uint32_t bOff = (uint32_t)((wn + (lmat >> 1) * 8 + lr) * PITCHB + (lmat & 1) * 16);

    float acc[4][4][4];
#pragma unroll
    for (int i = 0; i < 4; i++)
#pragma unroll
        for (int j = 0; j < 4; j++)
#pragma unroll
            for (int r = 0; r < 4; r++) acc[i][j][r] = 0.f;

    load_stage(sbase + 0 * STG_BYTES, 0,  t, A, B, m0, n0, K);
    CP_COMMIT();
    load_stage(sbase + 1 * STG_BYTES, BK, t, A, B, m0, n0, K);
    CP_COMMIT();

    for (int kt = 0; kt < KT; kt++) {
        CP_WAIT1();
        __syncthreads();
        if (kt + 2 < KT)
            load_stage(sbase + ((kt + 2) % 3) * STG_BYTES, (kt + 2) * BK,
                       t, A, B, m0, n0, K);
        CP_COMMIT();

        const uint32_t sb = sbase + (kt % 3) * STG_BYTES;
#pragma unroll
        for (int ks = 0; ks < 2; ks++) {
            uint32_t ah[4][4], bh[2][4];
            const uint32_t kb = ks * 32;
#pragma unroll
            for (int mt = 0; mt < 4; mt++)
                LDSM4(ah[mt], sb + 0 * ARR_BYTES + aOff + mt * (16 * PITCHB) + kb);
#pragma unroll
            for (int j = 0; j < 2; j++)
                LDSM4(bh[j], sb + 1 * ARR_BYTES + bOff + j * (16 * PITCHB) + kb);
#pragma unroll
            for (int mt = 0; mt < 4; mt++)
#pragma unroll
                for (int nt = 0; nt < 4; nt++)
                    MMA16816(acc[mt][nt], ah[mt],
                             bh[nt >> 1][(nt & 1) * 2], bh[nt >> 1][(nt & 1) * 2 + 1]);
        }
    }
    CP_WAIT0();
    __syncthreads();

    const int g = lane >> 2, tg = lane & 3;

    if (!QKV_EPI) {
        float* Cs = (float*)dyn_smem;      // [128][CPITCH]
#pragma unroll
        for (int mt = 0; mt < 4; mt++)
#pragma unroll
            for (int nt = 0; nt < 4; nt++) {
                int r0 = wm + mt * 16 + g;
                int cc = wn + nt * 8 + tg * 2;
                Cs[r0 * CPITCH + cc]       = acc[mt][nt][0];
                Cs[r0 * CPITCH + cc + 1]   = acc[mt][nt][1];
                Cs[(r0 + 8) * CPITCH + cc]     = acc[mt][nt][2];
                Cs[(r0 + 8) * CPITCH + cc + 1] = acc[mt][nt][3];
            }
        __syncthreads();

        const int q = t & 31;
        const int rb = t >> 5;
        float4 bv = *(const float4*)(bias + n0 + q * 4);
#pragma unroll
        for (int i = 0; i < 16; i++) {
            int row = rb + i * 8;
            float4 v = *(const float4*)&Cs[row * CPITCH + q * 4];
            v.x += bv.x; v.y += bv.y; v.z += bv.z; v.w += bv.w;
            *(float4*)(C + (size_t)(m0 + row) * N + n0 + q * 4) = v;
        }
    } else {
        // fused QKV epilogue: bias + fp16 cvt + per-head scatter
        float* Cs = (float*)dyn_smem;      // [128][CPITCH]
        float bv[4][2];
#pragma unroll
        for (int nt = 0; nt < 4; nt++) {
            int gc = n0 + wn + nt * 8 + tg * 2;
            bv[nt][0] = bias[gc];
            bv[nt][1] = bias[gc + 1];
        }
#pragma unroll
        for (int mt = 0; mt < 4; mt++)
#pragma unroll
            for (int nt = 0; nt < 4; nt++) {
                int r0 = wm + mt * 16 + g;
                int cc = wn + nt * 8 + tg * 2;
                Cs[r0 * CPITCH + cc]       = acc[mt][nt][0] + bv[nt][0];
                Cs[r0 * CPITCH + cc + 1]   = acc[mt][nt][1] + bv[nt][1];
                Cs[(r0 + 8) * CPITCH + cc]     = acc[mt][nt][2] + bv[nt][0];
                Cs[(r0 + 8) * CPITCH + cc + 1] = acc[mt][nt][3] + bv[nt][1];
            }
        __syncthreads();

        const int b = m0 >> 11;
        const int sb0 = m0 & 2047;
        const int h0 = (n0 & 1023) >> 6;

        if (n0 < 2048) {
            // Q or K: [bh][s][64] row-major, fp16
            __half* Dh = (n0 < 1024) ? g_Qh : g_Kh;
            const int u = t & 63;
            const int h = h0 + (u >> 5);
            const int d0 = (u * 2) & 63;
            const int rofs = t >> 6;
#pragma unroll
            for (int p = 0; p < 32; p++) {
                int row = p * 4 + rofs;
                float v0 = Cs[row * CPITCH + 2 * u];
                float v1 = Cs[row * CPITCH + 2 * u + 1];
                size_t dst = ((size_t)(b * NHEADS + h) * SEQ + sb0 + row) * HD + d0;
                *(uint32_t*)(Dh + dst) = pack2(v0, v1);
            }
        } else {
            // V: transposed [bh][d][s], fp16
            const int w = t >> 5;
            const int l = t & 31;
#pragma unroll
            for (int i = 0; i < 16; i++) {
                int c = w * 16 + i;
                int h = h0 + (c >> 6);
                int d = c & 63;
#pragma unroll
                for (int qq = 0; qq < 2; qq++) {
                    int r = 2 * (l + 32 * qq);
                    float v0 = Cs[r * CPITCH + c];
                    float v1 = Cs[(r + 1) * CPITCH + c];
                    size_t dst = ((size_t)(b * NHEADS + h) * HD + d) * SEQ + sb0 + r;
                    *(uint32_t*)(g_Vth + dst) = pack2(v0, v1);
                }
            }
        }
    }
}

// ---------------------------------------------------------------------------
// Tensor-core flash attention, pure fp16 operands, fp32 accumulate.
// Grid (SEQ/64, NHEADS, BATCH), 128 threads (4 warps, 16 rows each), 3 CTAs/SM.
// ---------------------------------------------------------------------------
#define APB 144
#define AARR (64 * APB)                 /* 9216 */
#define ASTG (2 * AARR)                 /* 18432: Kh, Vh */
#define ATTN_SMEM (AARR + 2 * ASTG)     /* 46080 */

__global__ void __launch_bounds__(128, 3) attn_tc(
    const __half* __restrict__ Qh,
    const __half* __restrict__ Kh,
    const __half* __restrict__ Vth)
{
    extern __shared__ char dyn_smem[];
    const int t = threadIdx.x, wid = t >> 5, lane = t & 31;
    const int qt = blockIdx.x, h = blockIdx.y, b = blockIdx.z;
    const int bh = b * NHEADS + h;
    const int q0 = qt * 64;

    const uint32_t sQh = smem_u32(dyn_smem);
    const uint32_t sStg = sQh + AARR;

    const size_t qkBase = (size_t)bh * SEQ * HD;
    const size_t vBase  = (size_t)bh * HD * SEQ;

    // Q tile
#pragma unroll
    for (int i = 0; i < 4; i++) {
        int idx = t + i * 128;          // 0..511
        int row = idx >> 3, ch = idx & 7;
        const __half* src = Qh + qkBase + (size_t)(q0 + row) * HD + ch * 8;
        CP_ASYNC16(sQh + row * APB + ch * 16, src);
    }
#define LOAD_KV_STAGE(sbuf, kt0) do { \
    int kk0 = (kt0) * 64; \
    _Pragma("unroll") \
    for (int i = 0; i < 8; i++) { \
        int idx = t + i * 128; \
        int arr = idx >> 9; \
        int u = idx & 511, row = u >> 3, ch = u & 7; \
        const __half* src; \
        if (arr == 0) src = Kh  + qkBase + (size_t)(kk0 + row) * HD + ch * 8; \
        else          src = Vth + vBase + (size_t)row * SEQ + kk0 + ch * 8; \
        CP_ASYNC16((sbuf) + arr * AARR + row * APB + ch * 16, src); \
    } \
} while (0)

    LOAD_KV_STAGE(sStg, 0);
    CP_COMMIT();
    LOAD_KV_STAGE(sStg + ASTG, 1);
    CP_COMMIT();

    const int wm = wid * 16;
    const int lmat = lane >> 3, lr = lane & 7;
    const uint32_t aOff = (uint32_t)((wm + (lmat & 1) * 8 + lr) * APB + (lmat >> 1) * 16);
    const uint32_t bOff = (uint32_t)(((lmat >> 1) * 8 + lr) * APB + (lmat & 1) * 16);
    const int g = lane >> 2, tg = lane & 3;

    float O[8][4];
#pragma unroll
    for (int i = 0; i < 8; i++)
#pragma unroll
        for (int j = 0; j < 4; j++) O[i][j] = 0.f;
    float m0r = -1e30f, m1r = -1e30f, l0 = 0.f, l1 = 0.f;

    const int NKT = SEQ / 64;
    for (int kt = 0; kt < NKT; kt++) {
        CP_WAIT1();
        __syncthreads();
        const uint32_t sb = sStg + (kt & 1) * ASTG;
        const uint32_t sKh = sb, sVh = sb + AARR;

        float S[8][4];
#pragma unroll
        for (int i = 0; i < 8; i++)
#pragma unroll
            for (int j = 0; j < 4; j++) S[i][j] = 0.f;

#pragma unroll
        for (int kc = 0; kc < 4; kc++) {
            uint32_t qh[4];
            LDSM4(qh, sQh + aOff + kc * 32);
#pragma unroll
            for (int j = 0; j < 4; j++) {
                uint32_t kh[4];
                LDSM4(kh, sKh + j * (16 * APB) + bOff + kc * 32);
                MMA16816(S[2 * j],     qh, kh[0], kh[1]);
                MMA16816(S[2 * j + 1], qh, kh[2], kh[3]);
            }
        }

        float rmax0 = -1e30f, rmax1 = -1e30f;
#pragma unroll
        for (int i = 0; i < 8; i++) {
            rmax0 = fmaxf(rmax0, fmaxf(S[i][0], S[i][1]));
            rmax1 = fmaxf(rmax1, fmaxf(S[i][2], S[i][3]));
        }
#pragma unroll
        for (int d = 1; d <= 2; d <<= 1) {
            rmax0 = fmaxf(rmax0, __shfl_xor_sync(0xffffffffu, rmax0, d));
            rmax1 = fmaxf(rmax1, __shfl_xor_sync(0xffffffffu, rmax1, d));
        }
        float mn0 = fmaxf(m0r, rmax0), mn1 = fmaxf(m1r, rmax1);
        float ms0 = mn0 * SC, ms1 = mn1 * SC;
        float sum0 = 0.f, sum1 = 0.f;
#pragma unroll
        for (int i = 0; i < 8; i++) {
            S[i][0] = ex2(fmaf(S[i][0], SC, -ms0));
            S[i][1] = ex2(fmaf(S[i][1], SC, -ms0));
            S[i][2] = ex2(fmaf(S[i][2], SC, -ms1));
            S[i][3] = ex2(fmaf(S[i][3], SC, -ms1));
            sum0 += S[i][0] + S[i][1];
            sum1 += S[i][2] + S[i][3];
        }
#pragma unroll
        for (int d = 1; d <= 2; d <<= 1) {
            sum0 += __shfl_xor_sync(0xffffffffu, sum0, d);
            sum1 += __shfl_xor_sync(0xffffffffu, sum1, d);
        }
        float c0 = ex2(SC * (m0r - mn0)), c1 = ex2(SC * (m1r - mn1));
        l0 = l0 * c0 + sum0;
        l1 = l1 * c1 + sum1;
        m0r = mn0; m1r = mn1;
#pragma unroll
        for (int i = 0; i < 8; i++) {
            O[i][0] *= c0; O[i][1] *= c0;
            O[i][2] *= c1; O[i][3] *= c1;
        }

#pragma unroll
        for (int kg = 0; kg < 4; kg++) {
            uint32_t ph[4];
            ph[0] = pack2(S[2 * kg][0],     S[2 * kg][1]);
            ph[1] = pack2(S[2 * kg][2],     S[2 * kg][3]);
            ph[2] = pack2(S[2 * kg + 1][0], S[2 * kg + 1][1]);
            ph[3] = pack2(S[2 * kg + 1][2], S[2 * kg + 1][3]);
#pragma unroll
            for (int dn = 0; dn < 4; dn++) {
                uint32_t vh[4];
                LDSM4(vh, sVh + dn * (16 * APB) + bOff + kg * 32);
                MMA16816(O[2 * dn],     ph, vh[0], vh[1]);
                MMA16816(O[2 * dn + 1], ph, vh[2], vh[3]);
            }
        }

        __syncthreads();
        if (kt + 2 < NKT) {
            LOAD_KV_STAGE(sStg + (kt & 1) * ASTG, kt + 2);
        }
        CP_COMMIT();
    }

    float inv0 = 1.0f / l0, inv1 = 1.0f / l1;
    int r0 = b * SEQ + q0 + wm + g;
    int r1 = r0 + 8;
#pragma unroll
    for (int ot = 0; ot < 8; ot++) {
        int col = h * HD + ot * 8 + tg * 2;
        *(uint32_t*)(g_ch + (size_t)r0 * DMODEL + col) =
            pack2(O[ot][0] * inv0, O[ot][1] * inv0);
        *(uint32_t*)(g_ch + (size_t)r1 * DMODEL + col) =
            pack2(O[ot][2] * inv1, O[ot][3] * inv1);
    }
}

extern "C" void kernel_launch(void* const* d_in, const int* in_sizes, int n_in,
                              void* d_out, int out_size)
{
    const float* x     = (const float*)d_in[0];
    const float* qkv_w = (const float*)d_in[1];
    const float* qkv_b = (const float*)d_in[2];
    const float* out_w = (const float*)d_in[3];
    const float* out_b = (const float*)d_in[4];
    float* out = (float*)d_out;

    void *p_xh, *p_qwh, *p_owh, *p_ch, *p_Qh, *p_Kh, *p_Vth;
    cudaGetSymbolAddress(&p_xh, g_xh);
    cudaGetSymbolAddress(&p_qwh, g_qwh);
    cudaGetSymbolAddress(&p_owh, g_owh);
    cudaGetSymbolAddress(&p_ch, g_ch);
    cudaGetSymbolAddress(&p_Qh, g_Qh);
    cudaGetSymbolAddress(&p_Kh, g_Kh);
    cudaGetSymbolAddress(&p_Vth, g_Vth);

    cudaFuncSetAttribute(gemm_tc<false>, cudaFuncAttributeMaxDynamicSharedMemorySize,
                         GEMM_SMEM);
    cudaFuncSetAttribute(gemm_tc<true>, cudaFuncAttributeMaxDynamicSharedMemorySize,
                         GEMM_SMEM);
    cudaFuncSetAttribute(attn_tc, cudaFuncAttributeMaxDynamicSharedMemorySize,
                         ATTN_SMEM);

    // convert inputs to fp16
    {
        int n4 = ROWS * DMODEL / 4;
        cvt_kernel<<<(n4 + 255) / 256, 256>>>((const float4*)x, (uint2*)p_xh, n4);
        n4 = NQKV * DMODEL / 4;
        cvt_kernel<<<(n4 + 255) / 256, 256>>>((const float4*)qkv_w, (uint2*)p_qwh, n4);
        n4 = DMODEL * DMODEL / 4;
        cvt_kernel<<<(n4 + 255) / 256, 256>>>((const float4*)out_w, (uint2*)p_owh, n4);
    }

    // 1) QKV projection with fused per-head scatter epilogue
    gemm_tc<true><<<dim3(NQKV / 128, ROWS / 128), 256, GEMM_SMEM>>>(
        (const __half*)p_xh, (const __half*)p_qwh,
        qkv_b, nullptr, NQKV, DMODEL);

    // 2) tensor-core flash attention -> ctx (fp16)
    attn_tc<<<dim3(SEQ / 64, NHEADS, BATCH), 128, ATTN_SMEM>>>(
        (const __half*)p_Qh, (const __half*)p_Kh, (const __half*)p_Vth);

    // 3) output projection
    gemm_tc<false><<<dim3(DMODEL / 128, ROWS / 128), 256, GEMM_SMEM>>>(
        (const __half*)p_ch, (const __half*)p_owh,
        out_b, out, DMODEL, DMODEL);
}

// round 9
// speedup vs baseline: 7.3950x; 1.0104x over previous
#include <cuda_runtime.h>
#include <cuda_fp16.h>
#include <cstdint>
#include <math.h>

#define DMODEL 1024
#define NHEADS 16
#define HD 64
#define BATCH 4
#define SEQ 2048
#define ROWS (BATCH * SEQ)   /* 8192 */
#define NQKV (3 * DMODEL)    /* 3072 */

// softmax scale folded with log2(e) (base-2 softmax)
#define SC (0.125f * 1.44269504088896340736f)

// ---------------------------------------------------------------------------
// Scratch (allocation-free __device__ globals), fp16 operands
// ---------------------------------------------------------------------------
__device__ __align__(256) __half g_xh[(size_t)ROWS * DMODEL];        // x
__device__ __align__(256) __half g_qwh[(size_t)NQKV * DMODEL];       // qkv_w
__device__ __align__(256) __half g_owh[(size_t)DMODEL * DMODEL];     // out_w
__device__ __align__(256) __half g_ch[(size_t)ROWS * DMODEL];        // ctx
// per-head attention operands, written by fused QKV epilogue
__device__ __align__(256) __half g_Qh[(size_t)ROWS * DMODEL];        // Q [bh][s][64]
__device__ __align__(256) __half g_Kh[(size_t)ROWS * DMODEL];        // K [bh][s][64]
__device__ __align__(256) __half g_Vth[(size_t)ROWS * DMODEL];       // V^T [bh][d][s]

// ---------------------------------------------------------------------------
// helpers
// ---------------------------------------------------------------------------
__device__ __forceinline__ uint32_t smem_u32(const void* p) {
    return (uint32_t)__cvta_generic_to_shared(p);
}

__device__ __forceinline__ uint32_t pack2(float a, float b) {
    __half2 h = __floats2half2_rn(a, b);
    return *reinterpret_cast<uint32_t*>(&h);
}

__device__ __forceinline__ float ex2(float x) {
    float y;
    asm("ex2.approx.ftz.f32 %0, %1;" : "=f"(y) : "f"(x));
    return y;
}

#define LDSM4(r, addr) \
    asm volatile("ldmatrix.sync.aligned.m8n8.x4.shared.b16 {%0,%1,%2,%3}, [%4];" \
                 : "=r"((r)[0]), "=r"((r)[1]), "=r"((r)[2]), "=r"((r)[3]) : "r"(addr))

#define MMA16816(d, a, b0, b1) \
    asm volatile("mma.sync.aligned.m16n8k16.row.col.f32.f16.f16.f32 " \
                 "{%0,%1,%2,%3}, {%4,%5,%6,%7}, {%8,%9}, {%0,%1,%2,%3};" \
                 : "+f"((d)[0]), "+f"((d)[1]), "+f"((d)[2]), "+f"((d)[3]) \
                 : "r"((a)[0]), "r"((a)[1]), "r"((a)[2]), "r"((a)[3]), \
                   "r"(b0), "r"(b1))

#define CP_ASYNC16(dst, src) \
    asm volatile("cp.async.cg.shared.global [%0], [%1], 16;" :: "r"(dst), "l"(src))
#define CP_COMMIT() asm volatile("cp.async.commit_group;" ::: "memory")
#define CP_WAIT1()  asm volatile("cp.async.wait_group 1;" ::: "memory")
#define CP_WAIT0()  asm volatile("cp.async.wait_group 0;" ::: "memory")

// ---------------------------------------------------------------------------
// fp32 -> fp16 convert (4-wide)
// ---------------------------------------------------------------------------
__global__ void cvt_kernel(const float4* __restrict__ in, uint2* __restrict__ hi, int n4) {
    int i = blockIdx.x * blockDim.x + threadIdx.x;
    if (i >= n4) return;
    float4 v = in[i];
    uint2 uh;
    uh.x = pack2(v.x, v.y);
    uh.y = pack2(v.z, v.w);
    hi[i] = uh;
}

// ---------------------------------------------------------------------------
// Tensor-core GEMM via mma.sync, pure fp16 operands, fp32 accumulate.
// C = A*B^T + bias.  BM=BN=128, BK=32, 256 thr, warp tile 64x32,
// 3-stage cp.async pipeline, 2 CTAs/SM.
// QKV_EPI: write Q/K per-head fp16 and V transposed fp16.
// ---------------------------------------------------------------------------
#define BK 32
#define PITCHB 80
#define ARR_BYTES (128 * PITCHB)        /* 10240 */
#define STG_BYTES (2 * ARR_BYTES)       /* 20480: A, B */
#define GEMM_SMEM 67584                 /* max(3*STG=61440, epilogue 128*132*4) */
#define CPITCH 132                      /* C staging pitch (floats) */

__device__ __forceinline__ void load_stage(
    uint32_t sb, int k0, int t,
    const __half* __restrict__ A, const __half* __restrict__ B,
    int m0, int n0, int K)
{
#pragma unroll
    for (int i = 0; i < 4; i++) {
        int idx = t + i * 256;          // 0..1023
        int arr = idx >> 9;             // 0:A 1:B
        int u   = idx & 511;
        int row = u & 127;
        int c   = u >> 7;               // 16B chunk 0..3
        const __half* base = arr ? B : A;
        int grow = (arr ? n0 : m0) + row;
        const __half* src = base + (size_t)grow * K + k0 + c * 8;
        uint32_t dst = sb + arr * ARR_BYTES + row * PITCHB + c * 16;
        CP_ASYNC16(dst, src);
    }
}

template <bool QKV_EPI>
__global__ void __launch_bounds__(256, 2) gemm_tc(
    const __half* __restrict__ A, const __half* __restrict__ B,
    const float* __restrict__ bias, float* __restrict__ C, int N, int K)
{
    extern __shared__ char dyn_smem[];
    const int t = threadIdx.x, wid = t >> 5, lane = t & 31;
    const int m0 = blockIdx.y * 128, n0 = blockIdx.x * 128;
    const int KT = K / BK;

    const uint32_t sbase = smem_u32(dyn_smem);
    const int wm = (wid >> 2) * 64;
    const int wn = (wid & 3) * 32;

    const int lmat = lane >> 3, lr = lane & 7;
    const uint32_t aOff = (uint32_t)((wm + (lmat & 1) * 8 + lr) * PITCHB + (lmat >> 1) * 16);
    const uint32_t bOff = (uint32_t)((wn + (lmat >> 1) * 8 + lr) * PITCHB + (lmat & 1) * 16);

    float acc[4][4][4];
#pragma unroll
    for (int i = 0; i < 4; i++)
#pragma unroll
        for (int j = 0; j < 4; j++)
#pragma unroll
            for (int r = 0; r < 4; r++) acc[i][j][r] = 0.f;

    load_stage(sbase + 0 * STG_BYTES, 0,  t, A, B, m0, n0, K);
    CP_COMMIT();
    load_stage(sbase + 1 * STG_BYTES, BK, t, A, B, m0, n0, K);
    CP_COMMIT();

    for (int kt = 0; kt < KT; kt++) {
        CP_WAIT1();
        __syncthreads();
        if (kt + 2 < KT)
            load_stage(sbase + ((kt + 2) % 3) * STG_BYTES, (kt + 2) * BK,
                       t, A, B, m0, n0, K);
        CP_COMMIT();

        const uint32_t sb = sbase + (kt % 3) * STG_BYTES;
#pragma unroll
        for (int ks = 0; ks < 2; ks++) {
            uint32_t ah[4][4], bh[2][4];
            const uint32_t kb = ks * 32;
#pragma unroll
            for (int mt = 0; mt < 4; mt++)
                LDSM4(ah[mt], sb + 0 * ARR_BYTES + aOff + mt * (16 * PITCHB) + kb);
#pragma unroll
            for (int j = 0; j < 2; j++)
                LDSM4(bh[j], sb + 1 * ARR_BYTES + bOff + j * (16 * PITCHB) + kb);
#pragma unroll
            for (int mt = 0; mt < 4; mt++)
#pragma unroll
                for (int nt = 0; nt < 4; nt++)
                    MMA16816(acc[mt][nt], ah[mt],
                             bh[nt >> 1][(nt & 1) * 2], bh[nt >> 1][(nt & 1) * 2 + 1]);
        }
    }
    CP_WAIT0();
    __syncthreads();

    const int g = lane >> 2, tg = lane & 3;

    if (!QKV_EPI) {
        float* Cs = (float*)dyn_smem;      // [128][CPITCH]
#pragma unroll
        for (int mt = 0; mt < 4; mt++)
#pragma unroll
            for (int nt = 0; nt < 4; nt++) {
                int r0 = wm + mt * 16 + g;
                int cc = wn + nt * 8 + tg * 2;
                Cs[r0 * CPITCH + cc]       = acc[mt][nt][0];
                Cs[r0 * CPITCH + cc + 1]   = acc[mt][nt][1];
                Cs[(r0 + 8) * CPITCH + cc]     = acc[mt][nt][2];
                Cs[(r0 + 8) * CPITCH + cc + 1] = acc[mt][nt][3];
            }
        __syncthreads();

        const int q = t & 31;
        const int rb = t >> 5;
        float4 bv = *(const float4*)(bias + n0 + q * 4);
#pragma unroll
        for (int i = 0; i < 16; i++) {
            int row = rb + i * 8;
            float4 v = *(const float4*)&Cs[row * CPITCH + q * 4];
            v.x += bv.x; v.y += bv.y; v.z += bv.z; v.w += bv.w;
            *(float4*)(C + (size_t)(m0 + row) * N + n0 + q * 4) = v;
        }
    } else {
        // fused QKV epilogue: bias + fp16 cvt + per-head scatter
        float* Cs = (float*)dyn_smem;      // [128][CPITCH]
        float bv[4][2];
#pragma unroll
        for (int nt = 0; nt < 4; nt++) {
            int gc = n0 + wn + nt * 8 + tg * 2;
            bv[nt][0] = bias[gc];
            bv[nt][1] = bias[gc + 1];
        }
#pragma unroll
        for (int mt = 0; mt < 4; mt++)
#pragma unroll
            for (int nt = 0; nt < 4; nt++) {
                int r0 = wm + mt * 16 + g;
                int cc = wn + nt * 8 + tg * 2;
                Cs[r0 * CPITCH + cc]       = acc[mt][nt][0] + bv[nt][0];
                Cs[r0 * CPITCH + cc + 1]   = acc[mt][nt][1] + bv[nt][1];
                Cs[(r0 + 8) * CPITCH + cc]     = acc[mt][nt][2] + bv[nt][0];
                Cs[(r0 + 8) * CPITCH + cc + 1] = acc[mt][nt][3] + bv[nt][1];
            }
        __syncthreads();

        const int b = m0 >> 11;
        const int sb0 = m0 & 2047;
        const int h0 = (n0 & 1023) >> 6;

        if (n0 < 2048) {
            // Q or K: [bh][s][64] row-major, fp16
            __half* Dh = (n0 < 1024) ? g_Qh : g_Kh;
            const int u = t & 63;
            const int h = h0 + (u >> 5);
            const int d0 = (u * 2) & 63;
            const int rofs = t >> 6;
#pragma unroll
            for (int p = 0; p < 32; p++) {
                int row = p * 4 + rofs;
                float v0 = Cs[row * CPITCH + 2 * u];
                float v1 = Cs[row * CPITCH + 2 * u + 1];
                size_t dst = ((size_t)(b * NHEADS + h) * SEQ + sb0 + row) * HD + d0;
                *(uint32_t*)(Dh + dst) = pack2(v0, v1);
            }
        } else {
            // V: transposed [bh][d][s], fp16
            const int w = t >> 5;
            const int l = t & 31;
#pragma unroll
            for (int i = 0; i < 16; i++) {
                int c = w * 16 + i;
                int h = h0 + (c >> 6);
                int d = c & 63;
#pragma unroll
                for (int qq = 0; qq < 2; qq++) {
                    int r = 2 * (l + 32 * qq);
                    float v0 = Cs[r * CPITCH + c];
                    float v1 = Cs[(r + 1) * CPITCH + c];
                    size_t dst = ((size_t)(b * NHEADS + h) * HD + d) * SEQ + sb0 + r;
                    *(uint32_t*)(g_Vth + dst) = pack2(v0, v1);
                }
            }
        }
    }
}

// ---------------------------------------------------------------------------
// Tensor-core flash attention, pure fp16 operands, fp32 accumulate.
// Q tile 128, K/V tiles 64.  Grid (SEQ/128, NHEADS, BATCH), 256 threads
// (8 warps, 16 q-rows each), 2 CTAs/SM.
// ---------------------------------------------------------------------------
#define APB 144
#define QARR (128 * APB)                /* 18432 */
#define AARR (64 * APB)                 /* 9216 */
#define ASTG (2 * AARR)                 /* 18432: Kh, Vh */
#define ATTN_SMEM (QARR + 2 * ASTG)     /* 55296 */

__global__ void __launch_bounds__(256, 2) attn_tc(
    const __half* __restrict__ Qh,
    const __half* __restrict__ Kh,
    const __half* __restrict__ Vth)
{
    extern __shared__ char dyn_smem[];
    const int t = threadIdx.x, wid = t >> 5, lane = t & 31;
    const int qt = blockIdx.x, h = blockIdx.y, b = blockIdx.z;
    const int bh = b * NHEADS + h;
    const int q0 = qt * 128;

    const uint32_t sQh = smem_u32(dyn_smem);
    const uint32_t sStg = sQh + QARR;

    const size_t qkBase = (size_t)bh * SEQ * HD;
    const size_t vBase  = (size_t)bh * HD * SEQ;

    // Q tile: 128 rows x 8 chunks = 1024 chunks
#pragma unroll
    for (int i = 0; i < 4; i++) {
        int idx = t + i * 256;
        int row = idx >> 3, ch = idx & 7;
        const __half* src = Qh + qkBase + (size_t)(q0 + row) * HD + ch * 8;
        CP_ASYNC16(sQh + row * APB + ch * 16, src);
    }
#define LOAD_KV_STAGE(sbuf, kt0) do { \
    int kk0 = (kt0) * 64; \
    _Pragma("unroll") \
    for (int i = 0; i < 4; i++) { \
        int idx = t + i * 256; \
        int arr = idx >> 9; \
        int u = idx & 511, row = u >> 3, ch = u & 7; \
        const __half* src; \
        if (arr == 0) src = Kh  + qkBase + (size_t)(kk0 + row) * HD + ch * 8; \
        else          src = Vth + vBase + (size_t)row * SEQ + kk0 + ch * 8; \
        CP_ASYNC16((sbuf) + arr * AARR + row * APB + ch * 16, src); \
    } \
} while (0)

    LOAD_KV_STAGE(sStg, 0);
    CP_COMMIT();
    LOAD_KV_STAGE(sStg + ASTG, 1);
    CP_COMMIT();

    const int wm = wid * 16;
    const int lmat = lane >> 3, lr = lane & 7;
    const uint32_t aOff = (uint32_t)((wm + (lmat & 1) * 8 + lr) * APB + (lmat >> 1) * 16);
    const uint32_t bOff = (uint32_t)(((lmat >> 1) * 8 + lr) * APB + (lmat & 1) * 16);
    const int g = lane >> 2, tg = lane & 3;

    float O[8][4];
#pragma unroll
    for (int i = 0; i < 8; i++)
#pragma unroll
        for (int j = 0; j < 4; j++) O[i][j] = 0.f;
    float m0r = -1e30f, m1r = -1e30f, l0 = 0.f, l1 = 0.f;

    const int NKT = SEQ / 64;
    for (int kt = 0; kt < NKT; kt++) {
        CP_WAIT1();
        __syncthreads();
        const uint32_t sb = sStg + (kt & 1) * ASTG;
        const uint32_t sKh = sb, sVh = sb + AARR;

        float S[8][4];
#pragma unroll
        for (int i = 0; i < 8; i++)
#pragma unroll
            for (int j = 0; j < 4; j++) S[i][j] = 0.f;

#pragma unroll
        for (int kc = 0; kc < 4; kc++) {
            uint32_t qh[4];
            LDSM4(qh, sQh + aOff + kc * 32);
#pragma unroll
            for (int j = 0; j < 4; j++) {
                uint32_t kh[4];
                LDSM4(kh, sKh + j * (16 * APB) + bOff + kc * 32);
                MMA16816(S[2 * j],     qh, kh[0], kh[1]);
                MMA16816(S[2 * j + 1], qh, kh[2], kh[3]);
            }
        }

        float rmax0 = -1e30f, rmax1 = -1e30f;
#pragma unroll
        for (int i = 0; i < 8; i++) {
            rmax0 = fmaxf(rmax0, fmaxf(S[i][0], S[i][1]));
            rmax1 = fmaxf(rmax1, fmaxf(S[i][2], S[i][3]));
        }
#pragma unroll
        for (int d = 1; d <= 2; d <<= 1) {
            rmax0 = fmaxf(rmax0, __shfl_xor_sync(0xffffffffu, rmax0, d));
            rmax1 = fmaxf(rmax1, __shfl_xor_sync(0xffffffffu, rmax1, d));
        }
        float mn0 = fmaxf(m0r, rmax0), mn1 = fmaxf(m1r, rmax1);
        float ms0 = mn0 * SC, ms1 = mn1 * SC;
        float sum0 = 0.f, sum1 = 0.f;
#pragma unroll
        for (int i = 0; i < 8; i++) {
            S[i][0] = ex2(fmaf(S[i][0], SC, -ms0));
            S[i][1] = ex2(fmaf(S[i][1], SC, -ms0));
            S[i][2] = ex2(fmaf(S[i][2], SC, -ms1));
            S[i][3] = ex2(fmaf(S[i][3], SC, -ms1));
            sum0 += S[i][0] + S[i][1];
            sum1 += S[i][2] + S[i][3];
        }
#pragma unroll
        for (int d = 1; d <= 2; d <<= 1) {
            sum0 += __shfl_xor_sync(0xffffffffu, sum0, d);
            sum1 += __shfl_xor_sync(0xffffffffu, sum1, d);
        }
        float c0 = ex2(SC * (m0r - mn0)), c1 = ex2(SC * (m1r - mn1));
        l0 = l0 * c0 + sum0;
        l1 = l1 * c1 + sum1;
        m0r = mn0; m1r = mn1;
#pragma unroll
        for (int i = 0; i < 8; i++) {
            O[i][0] *= c0; O[i][1] *= c0;
            O[i][2] *= c1; O[i][3] *= c1;
        }

#pragma unroll
        for (int kg = 0; kg < 4; kg++) {
            uint32_t ph[4];
            ph[0] = pack2(S[2 * kg][0],     S[2 * kg][1]);
            ph[1] = pack2(S[2 * kg][2],     S[2 * kg][3]);
            ph[2] = pack2(S[2 * kg + 1][0], S[2 * kg + 1][1]);
            ph[3] = pack2(S[2 * kg + 1][2], S[2 * kg + 1][3]);
#pragma unroll
            for (int dn = 0; dn < 4; dn++) {
                uint32_t vh[4];
                LDSM4(vh, sVh + dn * (16 * APB) + bOff + kg * 32);
                MMA16816(O[2 * dn],     ph, vh[0], vh[1]);
                MMA16816(O[2 * dn + 1], ph, vh[2], vh[3]);
            }
        }

        __syncthreads();
        if (kt + 2 < NKT) {
            LOAD_KV_STAGE(sStg + (kt & 1) * ASTG, kt + 2);
        }
        CP_COMMIT();
    }

    float inv0 = 1.0f / l0, inv1 = 1.0f / l1;
    int r0 = b * SEQ + q0 + wm + g;
    int r1 = r0 + 8;
#pragma unroll
    for (int ot = 0; ot < 8; ot++) {
        int col = h * HD + ot * 8 + tg * 2;
        *(uint32_t*)(g_ch + (size_t)r0 * DMODEL + col) =
            pack2(O[ot][0] * inv0, O[ot][1] * inv0);
        *(uint32_t*)(g_ch + (size_t)r1 * DMODEL + col) =
            pack2(O[ot][2] * inv1, O[ot][3] * inv1);
    }
}

extern "C" void kernel_launch(void* const* d_in, const int* in_sizes, int n_in,
                              void* d_out, int out_size)
{
    const float* x     = (const float*)d_in[0];
    const float* qkv_w = (const float*)d_in[1];
    const float* qkv_b = (const float*)d_in[2];
    const float* out_w = (const float*)d_in[3];
    const float* out_b = (const float*)d_in[4];
    float* out = (float*)d_out;

    void *p_xh, *p_qwh, *p_owh, *p_ch, *p_Qh, *p_Kh, *p_Vth;
    cudaGetSymbolAddress(&p_xh, g_xh);
    cudaGetSymbolAddress(&p_qwh, g_qwh);
    cudaGetSymbolAddress(&p_owh, g_owh);
    cudaGetSymbolAddress(&p_ch, g_ch);
    cudaGetSymbolAddress(&p_Qh, g_Qh);
    cudaGetSymbolAddress(&p_Kh, g_Kh);
    cudaGetSymbolAddress(&p_Vth, g_Vth);

    cudaFuncSetAttribute(gemm_tc<false>, cudaFuncAttributeMaxDynamicSharedMemorySize,
                         GEMM_SMEM);
    cudaFuncSetAttribute(gemm_tc<true>, cudaFuncAttributeMaxDynamicSharedMemorySize,
                         GEMM_SMEM);
    cudaFuncSetAttribute(attn_tc, cudaFuncAttributeMaxDynamicSharedMemorySize,
                         ATTN_SMEM);

    // convert inputs to fp16
    {
        int n4 = ROWS * DMODEL / 4;
        cvt_kernel<<<(n4 + 255) / 256, 256>>>((const float4*)x, (uint2*)p_xh, n4);
        n4 = NQKV * DMODEL / 4;
        cvt_kernel<<<(n4 + 255) / 256, 256>>>((const float4*)qkv_w, (uint2*)p_qwh, n4);
        n4 = DMODEL * DMODEL / 4;
        cvt_kernel<<<(n4 + 255) / 256, 256>>>((const float4*)out_w, (uint2*)p_owh, n4);
    }

    // 1) QKV projection with fused per-head scatter epilogue
    gemm_tc<true><<<dim3(NQKV / 128, ROWS / 128), 256, GEMM_SMEM>>>(
        (const __half*)p_xh, (const __half*)p_qwh,
        qkv_b, nullptr, NQKV, DMODEL);

    // 2) tensor-core flash attention -> ctx (fp16)
    attn_tc<<<dim3(SEQ / 128, NHEADS, BATCH), 256, ATTN_SMEM>>>(
        (const __half*)p_Qh, (const __half*)p_Kh, (const __half*)p_Vth);

    // 3) output projection
    gemm_tc<false><<<dim3(DMODEL / 128, ROWS / 128), 256, GEMM_SMEM>>>(
        (const __half*)p_ch, (const __half*)p_owh,
        out_b, out, DMODEL, DMODEL);
}

// round 10
// speedup vs baseline: 9.6742x; 1.3082x over previous
#include <cuda_runtime.h>
#include <cuda_fp16.h>
#include <cstdint>
#include <math.h>

#define DMODEL 1024
#define NHEADS 16
#define HD 64
#define BATCH 4
#define SEQ 2048
#define ROWS (BATCH * SEQ)   /* 8192 */
#define NQKV (3 * DMODEL)    /* 3072 */

// softmax scale folded with log2(e) (base-2 softmax)
#define SC (0.125f * 1.44269504088896340736f)

// ---------------------------------------------------------------------------
// Scratch (allocation-free __device__ globals), fp16 operands
// ---------------------------------------------------------------------------
__device__ __align__(256) __half g_xh[(size_t)ROWS * DMODEL];        // x
__device__ __align__(256) __half g_qwh[(size_t)NQKV * DMODEL];       // qkv_w
__device__ __align__(256) __half g_owh[(size_t)DMODEL * DMODEL];     // out_w
__device__ __align__(256) __half g_ch[(size_t)ROWS * DMODEL];        // ctx
// per-head attention operands, written by fused QKV epilogue
__device__ __align__(256) __half g_Qh[(size_t)ROWS * DMODEL];        // Q [bh][s][64]
__device__ __align__(256) __half g_Kh[(size_t)ROWS * DMODEL];        // K [bh][s][64]
__device__ __align__(256) __half g_Vth[(size_t)ROWS * DMODEL];       // V^T [bh][d][s]

// ---------------------------------------------------------------------------
// helpers
// ---------------------------------------------------------------------------
__device__ __forceinline__ uint32_t smem_u32(const void* p) {
    return (uint32_t)__cvta_generic_to_shared(p);
}

__device__ __forceinline__ uint32_t pack2(float a, float b) {
    __half2 h = __floats2half2_rn(a, b);
    return *reinterpret_cast<uint32_t*>(&h);
}

__device__ __forceinline__ float ex2(float x) {
    float y;
    asm("ex2.approx.ftz.f32 %0, %1;" : "=f"(y) : "f"(x));
    return y;
}

#define LDSM4(r, addr) \
    asm volatile("ldmatrix.sync.aligned.m8n8.x4.shared.b16 {%0,%1,%2,%3}, [%4];" \
                 : "=r"((r)[0]), "=r"((r)[1]), "=r"((r)[2]), "=r"((r)[3]) : "r"(addr))

#define MMA16816(d, a, b0, b1) \
    asm volatile("mma.sync.aligned.m16n8k16.row.col.f32.f16.f16.f32 " \
                 "{%0,%1,%2,%3}, {%4,%5,%6,%7}, {%8,%9}, {%0,%1,%2,%3};" \
                 : "+f"((d)[0]), "+f"((d)[1]), "+f"((d)[2]), "+f"((d)[3]) \
                 : "r"((a)[0]), "r"((a)[1]), "r"((a)[2]), "r"((a)[3]), \
                   "r"(b0), "r"(b1))

#define CP_ASYNC16(dst, src) \
    asm volatile("cp.async.cg.shared.global [%0], [%1], 16;" :: "r"(dst), "l"(src))
#define CP_COMMIT() asm volatile("cp.async.commit_group;" ::: "memory")
#define CP_WAIT1()  asm volatile("cp.async.wait_group 1;" ::: "memory")
#define CP_WAIT0()  asm volatile("cp.async.wait_group 0;" ::: "memory")

// ---------------------------------------------------------------------------
// fp32 -> fp16 convert (4-wide)
// ---------------------------------------------------------------------------
__global__ void cvt_kernel(const float4* __restrict__ in, uint2* __restrict__ hi, int n4) {
    int i = blockIdx.x * blockDim.x + threadIdx.x;
    if (i >= n4) return;
    float4 v = in[i];
    uint2 uh;
    uh.x = pack2(v.x, v.y);
    uh.y = pack2(v.z, v.w);
    hi[i] = uh;
}

// ---------------------------------------------------------------------------
// Tensor-core GEMM via mma.sync, pure fp16 operands, fp32 accumulate.
// C = A*B^T + bias.  BM=BN=128, BK=64 (one barrier per 64-k slab),
// 256 thr, warp tile 64x32, 3-stage cp.async pipeline, 2 CTAs/SM.
// QKV_EPI: write Q/K per-head fp16 and V transposed fp16.
// ---------------------------------------------------------------------------
#define BK 64
#define PITCHB 144                      /* 128B data + 16B pad, conflict-free */
#define ARR_BYTES (128 * PITCHB)        /* 18432 */
#define STG_BYTES (2 * ARR_BYTES)       /* 36864: A, B */
#define GEMM_SMEM (3 * STG_BYTES)       /* 110592 (>= epilogue 67584) */
#define CPITCH 132                      /* C staging pitch (floats) */

__device__ __forceinline__ void load_stage(
    uint32_t sb, int k0, int t,
    const __half* __restrict__ A, const __half* __restrict__ B,
    int m0, int n0, int K)
{
#pragma unroll
    for (int i = 0; i < 8; i++) {
        int idx = t + i * 256;          // 0..2047
        int arr = idx >> 10;            // 0:A 1:B
        int u   = idx & 1023;
        int row = u >> 3;               // 0..127
        int c   = u & 7;                // 16B chunk 0..7 (64 halves per row)
        const __half* base = arr ? B : A;
        int grow = (arr ? n0 : m0) + row;
        const __half* src = base + (size_t)grow * K + k0 + c * 8;
        uint32_t dst = sb + arr * ARR_BYTES + row * PITCHB + c * 16;
        CP_ASYNC16(dst, src);
    }
}

template <bool QKV_EPI>
__global__ void __launch_bounds__(256, 2) gemm_tc(
    const __half* __restrict__ A, const __half* __restrict__ B,
    const float* __restrict__ bias, float* __restrict__ C, int N, int K)
{
    extern __shared__ char dyn_smem[];
    const int t = threadIdx.x, wid = t >> 5, lane = t & 31;
    const int m0 = blockIdx.y * 128, n0 = blockIdx.x * 128;
    const int KT = K / BK;

    const uint32_t sbase = smem_u32(dyn_smem);
    const int wm = (wid >> 2) * 64;
    const int wn = (wid & 3) * 32;

    const int lmat = lane >> 3, lr = lane & 7;
    const uint32_t aOff = (uint32_t)((wm + (lmat & 1) * 8 + lr) * PITCHB + (lmat >> 1) * 16);
    const uint32_t bOff = (uint32_t)((wn + (lmat >> 1) * 8 + lr) * PITCHB + (lmat & 1) * 16);

    float acc[4][4][4];
#pragma unroll
    for (int i = 0; i < 4; i++)
#pragma unroll
        for (int j = 0; j < 4; j++)
#pragma unroll
            for (int r = 0; r < 4; r++) acc[i][j][r] = 0.f;

    load_stage(sbase + 0 * STG_BYTES, 0,  t, A, B, m0, n0, K);
    CP_COMMIT();
    load_stage(sbase + 1 * STG_BYTES, BK, t, A, B, m0, n0, K);
    CP_COMMIT();

    for (int kt = 0; kt < KT; kt++) {
        CP_WAIT1();
        __syncthreads();
        if (kt + 2 < KT)
            load_stage(sbase + ((kt + 2) % 3) * STG_BYTES, (kt + 2) * BK,
                       t, A, B, m0, n0, K);
        CP_COMMIT();

        const uint32_t sb = sbase + (kt % 3) * STG_BYTES;
#pragma unroll
        for (int ks = 0; ks < 4; ks++) {
            uint32_t ah[4][4], bh[2][4];
            const uint32_t kb = ks * 32;
#pragma unroll
            for (int mt = 0; mt < 4; mt++)
                LDSM4(ah[mt], sb + 0 * ARR_BYTES + aOff + mt * (16 * PITCHB) + kb);
#pragma unroll
            for (int j = 0; j < 2; j++)
                LDSM4(bh[j], sb + 1 * ARR_BYTES + bOff + j * (16 * PITCHB) + kb);
#pragma unroll
            for (int mt = 0; mt < 4; mt++)
#pragma unroll
                for (int nt = 0; nt < 4; nt++)
                    MMA16816(acc[mt][nt], ah[mt],
                             bh[nt >> 1][(nt & 1) * 2], bh[nt >> 1][(nt & 1) * 2 + 1]);
        }
    }
    CP_WAIT0();
    __syncthreads();

    const int g = lane >> 2, tg = lane & 3;

    if (!QKV_EPI) {
        float* Cs = (float*)dyn_smem;      // [128][CPITCH]
#pragma unroll
        for (int mt = 0; mt < 4; mt++)
#pragma unroll
            for (int nt = 0; nt < 4; nt++) {
                int r0 = wm + mt * 16 + g;
                int cc = wn + nt * 8 + tg * 2;
                Cs[r0 * CPITCH + cc]       = acc[mt][nt][0];
                Cs[r0 * CPITCH + cc + 1]   = acc[mt][nt][1];
                Cs[(r0 + 8) * CPITCH + cc]     = acc[mt][nt][2];
                Cs[(r0 + 8) * CPITCH + cc + 1] = acc[mt][nt][3];
            }
        __syncthreads();

        const int q = t & 31;
        const int rb = t >> 5;
        float4 bv = *(const float4*)(bias + n0 + q * 4);
#pragma unroll
        for (int i = 0; i < 16; i++) {
            int row = rb + i * 8;
            float4 v = *(const float4*)&Cs[row * CPITCH + q * 4];
            v.x += bv.x; v.y += bv.y; v.z += bv.z; v.w += bv.w;
            *(float4*)(C + (size_t)(m0 + row) * N + n0 + q * 4) = v;
        }
    } else {
        // fused QKV epilogue: bias + fp16 cvt + per-head scatter
        float* Cs = (float*)dyn_smem;      // [128][CPITCH]
        float bv[4][2];
#pragma unroll
        for (int nt = 0; nt < 4; nt++) {
            int gc = n0 + wn + nt * 8 + tg * 2;
            bv[nt][0] = bias[gc];
            bv[nt][1] = bias[gc + 1];
        }
#pragma unroll
        for (int mt = 0; mt < 4; mt++)
#pragma unroll
            for (int nt = 0; nt < 4; nt++) {
                int r0 = wm + mt * 16 + g;
                int cc = wn + nt * 8 + tg * 2;
                Cs[r0 * CPITCH + cc]       = acc[mt][nt][0] + bv[nt][0];
                Cs[r0 * CPITCH + cc + 1]   = acc[mt][nt][1] + bv[nt][1];
                Cs[(r0 + 8) * CPITCH + cc]     = acc[mt][nt][2] + bv[nt][0];
                Cs[(r0 + 8) * CPITCH + cc + 1] = acc[mt][nt][3] + bv[nt][1];
            }
        __syncthreads();

        const int b = m0 >> 11;
        const int sb0 = m0 & 2047;
        const int h0 = (n0 & 1023) >> 6;

        if (n0 < 2048) {
            // Q or K: [bh][s][64] row-major, fp16
            __half* Dh = (n0 < 1024) ? g_Qh : g_Kh;
            const int u = t & 63;
            const int h = h0 + (u >> 5);
            const int d0 = (u * 2) & 63;
            const int rofs = t >> 6;
#pragma unroll
            for (int p = 0; p < 32; p++) {
                int row = p * 4 + rofs;
                float v0 = Cs[row * CPITCH + 2 * u];
                float v1 = Cs[row * CPITCH + 2 * u + 1];
                size_t dst = ((size_t)(b * NHEADS + h) * SEQ + sb0 + row) * HD + d0;
                *(uint32_t*)(Dh + dst) = pack2(v0, v1);
            }
        } else {
            // V: transposed [bh][d][s], fp16
            const int w = t >> 5;
            const int l = t & 31;
#pragma unroll
            for (int i = 0; i < 16; i++) {
                int c = w * 16 + i;
                int h = h0 + (c >> 6);
                int d = c & 63;
#pragma unroll
                for (int qq = 0; qq < 2; qq++) {
                    int r = 2 * (l + 32 * qq);
                    float v0 = Cs[r * CPITCH + c];
                    float v1 = Cs[(r + 1) * CPITCH + c];
                    size_t dst = ((size_t)(b * NHEADS + h) * HD + d) * SEQ + sb0 + r;
                    *(uint32_t*)(g_Vth + dst) = pack2(v0, v1);
                }
            }
        }
    }
}

// ---------------------------------------------------------------------------
// Tensor-core flash attention, pure fp16 operands, fp32 accumulate.
// Q tile 128, K/V tiles 64.  Grid (SEQ/128, NHEADS, BATCH), 256 threads
// (8 warps, 16 q-rows each), 2 CTAs/SM.
// ---------------------------------------------------------------------------
#define APB 144
#define QARR (128 * APB)                /* 18432 */
#define AARR (64 * APB)                 /* 9216 */
#define ASTG (2 * AARR)                 /* 18432: Kh, Vh */
#define ATTN_SMEM (QARR + 2 * ASTG)     /* 55296 */

__global__ void __launch_bounds__(256, 2) attn_tc(
    const __half* __restrict__ Qh,
    const __half* __restrict__ Kh,
    const __half* __restrict__ Vth)
{
    extern __shared__ char dyn_smem[];
    const int t = threadIdx.x, wid = t >> 5, lane = t & 31;
    const int qt = blockIdx.x, h = blockIdx.y, b = blockIdx.z;
    const int bh = b * NHEADS + h;
    const int q0 = qt * 128;

    const uint32_t sQh = smem_u32(dyn_smem);
    const uint32_t sStg = sQh + QARR;

    const size_t qkBase = (size_t)bh * SEQ * HD;
    const size_t vBase  = (size_t)bh * HD * SEQ;

    // Q tile: 128 rows x 8 chunks = 1024 chunks
#pragma unroll
    for (int i = 0; i < 4; i++) {
        int idx = t + i * 256;
        int row = idx >> 3, ch = idx & 7;
        const __half* src = Qh + qkBase + (size_t)(q0 + row) * HD + ch * 8;
        CP_ASYNC16(sQh + row * APB + ch * 16, src);
    }
#define LOAD_KV_STAGE(sbuf, kt0) do { \
    int kk0 = (kt0) * 64; \
    _Pragma("unroll") \
    for (int i = 0; i < 4; i++) { \
        int idx = t + i * 256; \
        int arr = idx >> 9; \
        int u = idx & 511, row = u >> 3, ch = u & 7; \
        const __half* src; \
        if (arr == 0) src = Kh  + qkBase + (size_t)(kk0 + row) * HD + ch * 8; \
        else          src = Vth + vBase + (size_t)row * SEQ + kk0 + ch * 8; \
        CP_ASYNC16((sbuf) + arr * AARR + row * APB + ch * 16, src); \
    } \
} while (0)

    LOAD_KV_STAGE(sStg, 0);
    CP_COMMIT();
    LOAD_KV_STAGE(sStg + ASTG, 1);
    CP_COMMIT();

    const int wm = wid * 16;
    const int lmat = lane >> 3, lr = lane & 7;
    const uint32_t aOff = (uint32_t)((wm + (lmat & 1) * 8 + lr) * APB + (lmat >> 1) * 16);
    const uint32_t bOff = (uint32_t)(((lmat >> 1) * 8 + lr) * APB + (lmat & 1) * 16);
    const int g = lane >> 2, tg = lane & 3;

    float O[8][4];
#pragma unroll
    for (int i = 0; i < 8; i++)
#pragma unroll
        for (int j = 0; j < 4; j++) O[i][j] = 0.f;
    float m0r = -1e30f, m1r = -1e30f, l0 = 0.f, l1 = 0.f;

    const int NKT = SEQ / 64;
    for (int kt = 0; kt < NKT; kt++) {
        CP_WAIT1();
        __syncthreads();
        const uint32_t sb = sStg + (kt & 1) * ASTG;
        const uint32_t sKh = sb, sVh = sb + AARR;

        float S[8][4];
#pragma unroll
        for (int i = 0; i < 8; i++)
#pragma unroll
            for (int j = 0; j < 4; j++) S[i][j] = 0.f;

#pragma unroll
        for (int kc = 0; kc < 4; kc++) {
            uint32_t qh[4];
            LDSM4(qh, sQh + aOff + kc * 32);
#pragma unroll
            for (int j = 0; j < 4; j++) {
                uint32_t kh[4];
                LDSM4(kh, sKh + j * (16 * APB) + bOff + kc * 32);
                MMA16816(S[2 * j],     qh, kh[0], kh[1]);
                MMA16816(S[2 * j + 1], qh, kh[2], kh[3]);
            }
        }

        float rmax0 = -1e30f, rmax1 = -1e30f;
#pragma unroll
        for (int i = 0; i < 8; i++) {
            rmax0 = fmaxf(rmax0, fmaxf(S[i][0], S[i][1]));
            rmax1 = fmaxf(rmax1, fmaxf(S[i][2], S[i][3]));
        }
#pragma unroll
        for (int d = 1; d <= 2; d <<= 1) {
            rmax0 = fmaxf(rmax0, __shfl_xor_sync(0xffffffffu, rmax0, d));
            rmax1 = fmaxf(rmax1, __shfl_xor_sync(0xffffffffu, rmax1, d));
        }
        float mn0 = fmaxf(m0r, rmax0), mn1 = fmaxf(m1r, rmax1);
        float ms0 = mn0 * SC, ms1 = mn1 * SC;
        float sum0 = 0.f, sum1 = 0.f;
#pragma unroll
        for (int i = 0; i < 8; i++) {
            S[i][0] = ex2(fmaf(S[i][0], SC, -ms0));
            S[i][1] = ex2(fmaf(S[i][1], SC, -ms0));
            S[i][2] = ex2(fmaf(S[i][2], SC, -ms1));
            S[i][3] = ex2(fmaf(S[i][3], SC, -ms1));
            sum0 += S[i][0] + S[i][1];
            sum1 += S[i][2] + S[i][3];
        }
#pragma unroll
        for (int d = 1; d <= 2; d <<= 1) {
            sum0 += __shfl_xor_sync(0xffffffffu, sum0, d);
            sum1 += __shfl_xor_sync(0xffffffffu, sum1, d);
        }
        float c0 = ex2(SC * (m0r - mn0)), c1 = ex2(SC * (m1r - mn1));
        l0 = l0 * c0 + sum0;
        l1 = l1 * c1 + sum1;
        m0r = mn0; m1r = mn1;
#pragma unroll
        for (int i = 0; i < 8; i++) {
            O[i][0] *= c0; O[i][1] *= c0;
            O[i][2] *= c1; O[i][3] *= c1;
        }

#pragma unroll
        for (int kg = 0; kg < 4; kg++) {
            uint32_t ph[4];
            ph[0] = pack2(S[2 * kg][0],     S[2 * kg][1]);
            ph[1] = pack2(S[2 * kg][2],     S[2 * kg][3]);
            ph[2] = pack2(S[2 * kg + 1][0], S[2 * kg + 1][1]);
            ph[3] = pack2(S[2 * kg + 1][2], S[2 * kg + 1][3]);
#pragma unroll
            for (int dn = 0; dn < 4; dn++) {
                uint32_t vh[4];
                LDSM4(vh, sVh + dn * (16 * APB) + bOff + kg * 32);
                MMA16816(O[2 * dn],     ph, vh[0], vh[1]);
                MMA16816(O[2 * dn + 1], ph, vh[2], vh[3]);
            }
        }

        __syncthreads();
        if (kt + 2 < NKT) {
            LOAD_KV_STAGE(sStg + (kt & 1) * ASTG, kt + 2);
        }
        CP_COMMIT();
    }

    float inv0 = 1.0f / l0, inv1 = 1.0f / l1;
    int r0 = b * SEQ + q0 + wm + g;
    int r1 = r0 + 8;
#pragma unroll
    for (int ot = 0; ot < 8; ot++) {
        int col = h * HD + ot * 8 + tg * 2;
        *(uint32_t*)(g_ch + (size_t)r0 * DMODEL + col) =
            pack2(O[ot][0] * inv0, O[ot][1] * inv0);
        *(uint32_t*)(g_ch + (size_t)r1 * DMODEL + col) =
            pack2(O[ot][2] * inv1, O[ot][3] * inv1);
    }
}

extern "C" void kernel_launch(void* const* d_in, const int* in_sizes, int n_in,
                              void* d_out, int out_size)
{
    const float* x     = (const float*)d_in[0];
    const float* qkv_w = (const float*)d_in[1];
    const float* qkv_b = (const float*)d_in[2];
    const float* out_w = (const float*)d_in[3];
    const float* out_b = (const float*)d_in[4];
    float* out = (float*)d_out;

    void *p_xh, *p_qwh, *p_owh, *p_ch, *p_Qh, *p_Kh, *p_Vth;
    cudaGetSymbolAddress(&p_xh, g_xh);
    cudaGetSymbolAddress(&p_qwh, g_qwh);
    cudaGetSymbolAddress(&p_owh, g_owh);
    cudaGetSymbolAddress(&p_ch, g_ch);
    cudaGetSymbolAddress(&p_Qh, g_Qh);
    cudaGetSymbolAddress(&p_Kh, g_Kh);
    cudaGetSymbolAddress(&p_Vth, g_Vth);

    cudaFuncSetAttribute(gemm_tc<false>, cudaFuncAttributeMaxDynamicSharedMemorySize,
                         GEMM_SMEM);
    cudaFuncSetAttribute(gemm_tc<true>, cudaFuncAttributeMaxDynamicSharedMemorySize,
                         GEMM_SMEM);
    cudaFuncSetAttribute(attn_tc, cudaFuncAttributeMaxDynamicSharedMemorySize,
                         ATTN_SMEM);

    // convert inputs to fp16
    {
        int n4 = ROWS * DMODEL / 4;
        cvt_kernel<<<(n4 + 255) / 256, 256>>>((const float4*)x, (uint2*)p_xh, n4);
        n4 = NQKV * DMODEL / 4;
        cvt_kernel<<<(n4 + 255) / 256, 256>>>((const float4*)qkv_w, (uint2*)p_qwh, n4);
        n4 = DMODEL * DMODEL / 4;
        cvt_kernel<<<(n4 + 255) / 256, 256>>>((const float4*)out_w, (uint2*)p_owh, n4);
    }

    // 1) QKV projection with fused per-head scatter epilogue
    gemm_tc<true><<<dim3(NQKV / 128, ROWS / 128), 256, GEMM_SMEM>>>(
        (const __half*)p_xh, (const __half*)p_qwh,
        qkv_b, nullptr, NQKV, DMODEL);

    // 2) tensor-core flash attention -> ctx (fp16)
    attn_tc<<<dim3(SEQ / 128, NHEADS, BATCH), 256, ATTN_SMEM>>>(
        (const __half*)p_Qh, (const __half*)p_Kh, (const __half*)p_Vth);

    // 3) output projection
    gemm_tc<false><<<dim3(DMODEL / 128, ROWS / 128), 256, GEMM_SMEM>>>(
        (const __half*)p_ch, (const __half*)p_owh,
        out_b, out, DMODEL, DMODEL);
}